// round 1
// baseline (speedup 1.0000x reference)
#include <cuda_runtime.h>
#include <math.h>

#define BB 8
#define C1 64
#define C2 128
#define HH 64
#define WW 64
#define H2 128
#define W2 128

#define R_ELEMS (BB*C1*H2*W2)   /* 8388608 */
#define MAP_ELEMS (BB*H2*W2)    /* 131072  */

// Scratch (allocation-free: __device__ globals)
__device__ float g_dep[R_ELEMS];
__device__ float g_t1[R_ELEMS];
__device__ float g_r1[R_ELEMS];
__device__ float g_r2[R_ELEMS];
__device__ float g_im[MAP_ELEMS];
__device__ float g_im1[MAP_ELEMS];
__device__ float g_inc[MAP_ELEMS];
__device__ float g_outmap[MAP_ELEMS];

// ---------------------------------------------------------------------------
// 1) bilinear x2 (align_corners) + sigmoid for both maps.
//    up2(1-x) == 1-up2(x), so one interpolation, two sigmoids.
// ---------------------------------------------------------------------------
__global__ void upsample_sig_kernel(const float* __restrict__ in_map) {
    int idx = blockIdx.x * blockDim.x + threadIdx.x;
    if (idx >= MAP_ELEMS) return;
    int b = idx / (H2 * W2);
    int p = idx % (H2 * W2);
    int oy = p / W2, ox = p % W2;
    float cy = oy * (63.0f / 127.0f);
    float cx = ox * (63.0f / 127.0f);
    int y0 = (int)floorf(cy); int y1 = min(y0 + 1, HH - 1);
    int x0 = (int)floorf(cx); int x1 = min(x0 + 1, WW - 1);
    float wy = cy - (float)y0, wx = cx - (float)x0;
    const float* m = in_map + b * HH * WW;
    float v00 = m[y0 * WW + x0], v01 = m[y0 * WW + x1];
    float v10 = m[y1 * WW + x0], v11 = m[y1 * WW + x1];
    float u = v00 * (1.f - wy) * (1.f - wx) + v01 * (1.f - wy) * wx
            + v10 * wy * (1.f - wx)        + v11 * wy * wx;
    g_im[idx]  = 1.0f / (1.0f + expf(-u));
    g_im1[idx] = 1.0f / (1.0f + expf(-(1.0f - u)));
}

// ---------------------------------------------------------------------------
// 2) inc = dilate3x3(im) - im
// ---------------------------------------------------------------------------
__device__ __forceinline__ float max3x3(const float* m, int oy, int ox) {
    float mx = -3.4e38f;
    #pragma unroll
    for (int dy = -1; dy <= 1; dy++) {
        int y = oy + dy;
        if (y < 0 || y >= H2) continue;
        #pragma unroll
        for (int dx = -1; dx <= 1; dx++) {
            int x = ox + dx;
            if (x < 0 || x >= W2) continue;
            mx = fmaxf(mx, m[y * W2 + x]);
        }
    }
    return mx;
}

__global__ void inc_kernel() {
    int idx = blockIdx.x * blockDim.x + threadIdx.x;
    if (idx >= MAP_ELEMS) return;
    int b = idx / (H2 * W2);
    int p = idx % (H2 * W2);
    int oy = p / W2, ox = p % W2;
    const float* m = g_im + b * H2 * W2;
    g_inc[idx] = max3x3(m, oy, ox) - m[oy * W2 + ox];
}

// ---------------------------------------------------------------------------
// 3) outmap = inc + (dilate(inc)-inc) + (dilate(im1)-im1)
//           = dilate(inc) + dilate(im1) - im1
// ---------------------------------------------------------------------------
__global__ void outmap_kernel() {
    int idx = blockIdx.x * blockDim.x + threadIdx.x;
    if (idx >= MAP_ELEMS) return;
    int b = idx / (H2 * W2);
    int p = idx % (H2 * W2);
    int oy = p / W2, ox = p % W2;
    const float* mi = g_inc + b * H2 * W2;
    const float* m1 = g_im1 + b * H2 * W2;
    g_outmap[idx] = max3x3(mi, oy, ox) + max3x3(m1, oy, ox) - m1[oy * W2 + ox];
}

// ---------------------------------------------------------------------------
// 4) up-conv 7x7 (128->256, 64x64) + bias + BN + ReLU + pixel_shuffle -> g_dep
//    32x32 tile, 8 oc/block, each thread a 2x2 quad (offsets 0/16).
// ---------------------------------------------------------------------------
__global__ __launch_bounds__(256) void up_conv_kernel(
    const float* __restrict__ x, const float* __restrict__ w,
    const float* __restrict__ bias, const float* __restrict__ bn)
{
    __shared__ float sIn[38 * 38];
    __shared__ float sW[8 * 49];
    int tid = threadIdx.x;
    int tx = tid & 15, ty = tid >> 4;
    int bx = blockIdx.x, by = blockIdx.y;
    int b = blockIdx.z >> 5;
    int oc_base = (blockIdx.z & 31) * 8;
    int y0 = by * 32 - 3, x0 = bx * 32 - 3;

    float acc[8][2][2];
    #pragma unroll
    for (int o = 0; o < 8; o++)
        #pragma unroll
        for (int dy = 0; dy < 2; dy++)
            #pragma unroll
            for (int dx = 0; dx < 2; dx++) acc[o][dy][dx] = 0.0f;

    for (int ci = 0; ci < C2; ci++) {
        const float* xin = x + (b * C2 + ci) * HH * WW;
        for (int i = tid; i < 38 * 38; i += 256) {
            int r = i / 38, c = i % 38;
            int gy = y0 + r, gx = x0 + c;
            sIn[i] = (gy >= 0 && gy < HH && gx >= 0 && gx < WW) ? xin[gy * WW + gx] : 0.0f;
        }
        for (int i = tid; i < 8 * 49; i += 256) {
            int o = i / 49, k = i % 49;
            sW[i] = w[((oc_base + o) * C2 + ci) * 49 + k];
        }
        __syncthreads();
        #pragma unroll 1
        for (int kh = 0; kh < 7; kh++) {
            #pragma unroll
            for (int kw = 0; kw < 7; kw++) {
                float wv[8];
                #pragma unroll
                for (int o = 0; o < 8; o++) wv[o] = sW[o * 49 + kh * 7 + kw];
                #pragma unroll
                for (int dy = 0; dy < 2; dy++)
                    #pragma unroll
                    for (int dx = 0; dx < 2; dx++) {
                        float v = sIn[(ty + dy * 16 + kh) * 38 + (tx + dx * 16 + kw)];
                        #pragma unroll
                        for (int o = 0; o < 8; o++)
                            acc[o][dy][dx] = fmaf(wv[o], v, acc[o][dy][dx]);
                    }
            }
        }
        __syncthreads();
    }

    #pragma unroll
    for (int o = 0; o < 8; o++) {
        int c4 = oc_base + o;
        float gam = bn[c4], bet = bn[256 + c4], mu = bn[512 + c4], var = bn[768 + c4];
        float scale = gam * rsqrtf(var + 1e-5f);
        float off = (bias[c4] - mu) * scale + bet;
        int c = c4 >> 2, a = (c4 >> 1) & 1, d = c4 & 1;
        #pragma unroll
        for (int dy = 0; dy < 2; dy++)
            #pragma unroll
            for (int dx = 0; dx < 2; dx++) {
                int h = by * 32 + ty + dy * 16;
                int ww2 = bx * 32 + tx + dx * 16;
                float v = fmaxf(fmaf(acc[o][dy][dx], scale, off), 0.0f);
                g_dep[((b * C1 + c) * H2 + 2 * h + a) * W2 + 2 * ww2 + d] = v;
            }
    }
}

// ---------------------------------------------------------------------------
// 5) conv2 3x3 (64->64, 128x128) on (outmap * cur_x); t1 = dep + beta*(conv+b)
// ---------------------------------------------------------------------------
__global__ __launch_bounds__(256) void conv2_kernel(
    const float* __restrict__ x, const float* __restrict__ w,
    const float* __restrict__ bias, const float* __restrict__ beta)
{
    __shared__ float sIn[34 * 34];
    __shared__ float sMap[34 * 34];
    __shared__ float sW[8 * 9];
    int tid = threadIdx.x;
    int tx = tid & 15, ty = tid >> 4;
    int bx = blockIdx.x, by = blockIdx.y;
    int b = blockIdx.z >> 3;
    int oc_base = (blockIdx.z & 7) * 8;
    int y0 = by * 32 - 1, x0 = bx * 32 - 1;

    const float* om = g_outmap + b * H2 * W2;
    for (int i = tid; i < 34 * 34; i += 256) {
        int r = i / 34, c = i % 34;
        int gy = y0 + r, gx = x0 + c;
        sMap[i] = (gy >= 0 && gy < H2 && gx >= 0 && gx < W2) ? om[gy * W2 + gx] : 0.0f;
    }
    __syncthreads();

    float acc[8][2][2];
    #pragma unroll
    for (int o = 0; o < 8; o++)
        #pragma unroll
        for (int dy = 0; dy < 2; dy++)
            #pragma unroll
            for (int dx = 0; dx < 2; dx++) acc[o][dy][dx] = 0.0f;

    for (int ci = 0; ci < C1; ci++) {
        const float* xin = x + (b * C1 + ci) * H2 * W2;
        for (int i = tid; i < 34 * 34; i += 256) {
            int r = i / 34, c = i % 34;
            int gy = y0 + r, gx = x0 + c;
            float v = (gy >= 0 && gy < H2 && gx >= 0 && gx < W2) ? xin[gy * W2 + gx] : 0.0f;
            sIn[i] = v * sMap[i];
        }
        for (int i = tid; i < 8 * 9; i += 256) {
            int o = i / 9, k = i % 9;
            sW[i] = w[((oc_base + o) * C1 + ci) * 9 + k];
        }
        __syncthreads();
        #pragma unroll
        for (int kh = 0; kh < 3; kh++)
            #pragma unroll
            for (int kw = 0; kw < 3; kw++) {
                float wv[8];
                #pragma unroll
                for (int o = 0; o < 8; o++) wv[o] = sW[o * 9 + kh * 3 + kw];
                #pragma unroll
                for (int dy = 0; dy < 2; dy++)
                    #pragma unroll
                    for (int dx = 0; dx < 2; dx++) {
                        float v = sIn[(ty + dy * 16 + kh) * 34 + (tx + dx * 16 + kw)];
                        #pragma unroll
                        for (int o = 0; o < 8; o++)
                            acc[o][dy][dx] = fmaf(wv[o], v, acc[o][dy][dx]);
                    }
            }
        __syncthreads();
    }

    float bt = beta[0];
    #pragma unroll
    for (int o = 0; o < 8; o++) {
        int oc = oc_base + o;
        float bz = bias[oc];
        #pragma unroll
        for (int dy = 0; dy < 2; dy++)
            #pragma unroll
            for (int dx = 0; dx < 2; dx++) {
                int y = by * 32 + ty + dy * 16;
                int xx = bx * 32 + tx + dx * 16;
                int idx = ((b * C1 + oc) * H2 + y) * W2 + xx;
                g_t1[idx] = g_dep[idx] + bt * (acc[o][dy][dx] + bz);
            }
    }
}

// ---------------------------------------------------------------------------
// 6) generic conv3x3 (64->64, 128x128) + bias + BN + ReLU
// ---------------------------------------------------------------------------
__global__ __launch_bounds__(256) void conv3_bn_relu_kernel(
    const float* __restrict__ in, const float* __restrict__ w,
    const float* __restrict__ bias, const float* __restrict__ bn,
    float* __restrict__ out)
{
    __shared__ float sIn[34 * 34];
    __shared__ float sW[8 * 9];
    int tid = threadIdx.x;
    int tx = tid & 15, ty = tid >> 4;
    int bx = blockIdx.x, by = blockIdx.y;
    int b = blockIdx.z >> 3;
    int oc_base = (blockIdx.z & 7) * 8;
    int y0 = by * 32 - 1, x0 = bx * 32 - 1;

    float acc[8][2][2];
    #pragma unroll
    for (int o = 0; o < 8; o++)
        #pragma unroll
        for (int dy = 0; dy < 2; dy++)
            #pragma unroll
            for (int dx = 0; dx < 2; dx++) acc[o][dy][dx] = 0.0f;

    for (int ci = 0; ci < C1; ci++) {
        const float* xin = in + (b * C1 + ci) * H2 * W2;
        for (int i = tid; i < 34 * 34; i += 256) {
            int r = i / 34, c = i % 34;
            int gy = y0 + r, gx = x0 + c;
            sIn[i] = (gy >= 0 && gy < H2 && gx >= 0 && gx < W2) ? xin[gy * W2 + gx] : 0.0f;
        }
        for (int i = tid; i < 8 * 9; i += 256) {
            int o = i / 9, k = i % 9;
            sW[i] = w[((oc_base + o) * C1 + ci) * 9 + k];
        }
        __syncthreads();
        #pragma unroll
        for (int kh = 0; kh < 3; kh++)
            #pragma unroll
            for (int kw = 0; kw < 3; kw++) {
                float wv[8];
                #pragma unroll
                for (int o = 0; o < 8; o++) wv[o] = sW[o * 9 + kh * 3 + kw];
                #pragma unroll
                for (int dy = 0; dy < 2; dy++)
                    #pragma unroll
                    for (int dx = 0; dx < 2; dx++) {
                        float v = sIn[(ty + dy * 16 + kh) * 34 + (tx + dx * 16 + kw)];
                        #pragma unroll
                        for (int o = 0; o < 8; o++)
                            acc[o][dy][dx] = fmaf(wv[o], v, acc[o][dy][dx]);
                    }
            }
        __syncthreads();
    }

    #pragma unroll
    for (int o = 0; o < 8; o++) {
        int oc = oc_base + o;
        float gam = bn[oc], bet = bn[64 + oc], mu = bn[128 + oc], var = bn[192 + oc];
        float scale = gam * rsqrtf(var + 1e-5f);
        float off = (bias[oc] - mu) * scale + bet;
        #pragma unroll
        for (int dy = 0; dy < 2; dy++)
            #pragma unroll
            for (int dx = 0; dx < 2; dx++) {
                int y = by * 32 + ty + dy * 16;
                int xx = bx * 32 + tx + dx * 16;
                float v = fmaxf(fmaf(acc[o][dy][dx], scale, off), 0.0f);
                out[((b * C1 + oc) * H2 + y) * W2 + xx] = v;
            }
    }
}

// ---------------------------------------------------------------------------
// 7) out-conv 7x7 (64->1, 128x128) + bias
// ---------------------------------------------------------------------------
__global__ __launch_bounds__(256) void out_conv_kernel(
    const float* __restrict__ rin, const float* __restrict__ w,
    const float* __restrict__ bias, float* __restrict__ out)
{
    __shared__ float sIn[22 * 22];
    __shared__ float sW[49];
    int tid = threadIdx.x;
    int tx = tid & 15, ty = tid >> 4;
    int bx = blockIdx.x, by = blockIdx.y;
    int b = blockIdx.z;
    int y0 = by * 16 - 3, x0 = bx * 16 - 3;

    float acc = 0.0f;
    for (int ci = 0; ci < C1; ci++) {
        const float* xin = rin + (b * C1 + ci) * H2 * W2;
        for (int i = tid; i < 22 * 22; i += 256) {
            int r = i / 22, c = i % 22;
            int gy = y0 + r, gx = x0 + c;
            sIn[i] = (gy >= 0 && gy < H2 && gx >= 0 && gx < W2) ? xin[gy * W2 + gx] : 0.0f;
        }
        if (tid < 49) sW[tid] = w[ci * 49 + tid];
        __syncthreads();
        #pragma unroll 1
        for (int kh = 0; kh < 7; kh++)
            #pragma unroll
            for (int kw = 0; kw < 7; kw++)
                acc = fmaf(sIn[(ty + kh) * 22 + (tx + kw)], sW[kh * 7 + kw], acc);
        __syncthreads();
    }
    int y = by * 16 + ty, xx = bx * 16 + tx;
    out[b * H2 * W2 + y * W2 + xx] = acc + bias[0];
}

// ---------------------------------------------------------------------------
extern "C" void kernel_launch(void* const* d_in, const int* in_sizes, int n_in,
                              void* d_out, int out_size) {
    const float* cur_x   = (const float*)d_in[0];
    const float* dep_x   = (const float*)d_in[1];
    const float* in_map  = (const float*)d_in[2];
    const float* up_w    = (const float*)d_in[3];
    const float* up_b    = (const float*)d_in[4];
    const float* up_bn   = (const float*)d_in[5];
    const float* conv2_w = (const float*)d_in[6];
    const float* conv2_b = (const float*)d_in[7];
    const float* d1_w    = (const float*)d_in[8];
    const float* d1_b    = (const float*)d_in[9];
    const float* d1_bn   = (const float*)d_in[10];
    const float* d2_w    = (const float*)d_in[11];
    const float* d2_b    = (const float*)d_in[12];
    const float* d2_bn   = (const float*)d_in[13];
    const float* d3_w    = (const float*)d_in[14];
    const float* d3_b    = (const float*)d_in[15];
    const float* d3_bn   = (const float*)d_in[16];
    const float* out_w   = (const float*)d_in[17];
    const float* out_b   = (const float*)d_in[18];
    const float* beta    = (const float*)d_in[19];
    float* out = (float*)d_out;

    float *p_t1, *p_r1, *p_r2;
    cudaGetSymbolAddress((void**)&p_t1, g_t1);
    cudaGetSymbolAddress((void**)&p_r1, g_r1);
    cudaGetSymbolAddress((void**)&p_r2, g_r2);

    // map pipeline
    upsample_sig_kernel<<<MAP_ELEMS / 256, 256>>>(in_map);
    inc_kernel<<<MAP_ELEMS / 256, 256>>>();
    outmap_kernel<<<MAP_ELEMS / 256, 256>>>();

    // big up-conv + fused BN/ReLU/pixel-shuffle
    up_conv_kernel<<<dim3(2, 2, 256), 256>>>(dep_x, up_w, up_b, up_bn);

    // gated conv2 + residual combine -> t1
    conv2_kernel<<<dim3(4, 4, 64), 256>>>(cur_x, conv2_w, conv2_b, beta);

    // three conv3x3+BN+ReLU stages; last writes r directly into d_out
    conv3_bn_relu_kernel<<<dim3(4, 4, 64), 256>>>(p_t1, d1_w, d1_b, d1_bn, p_r1);
    conv3_bn_relu_kernel<<<dim3(4, 4, 64), 256>>>(p_r1, d2_w, d2_b, d2_bn, p_r2);
    conv3_bn_relu_kernel<<<dim3(4, 4, 64), 256>>>(p_r2, d3_w, d3_b, d3_bn, out);

    // final 7x7 conv -> output_map appended after r
    out_conv_kernel<<<dim3(8, 8, 8), 256>>>(out, out_w, out_b, out + R_ELEMS);
}

// round 2
// speedup vs baseline: 1.2190x; 1.2190x over previous
#include <cuda_runtime.h>
#include <math.h>

#define BB 8
#define C1 64
#define C2 128
#define HH 64
#define WW 64
#define H2 128
#define W2 128

#define R_ELEMS (BB*C1*H2*W2)   /* 8388608 */
#define MAP_ELEMS (BB*H2*W2)    /* 131072  */

// Scratch (allocation-free: __device__ globals)
__device__ float g_dep[R_ELEMS];
__device__ float g_t1[R_ELEMS];
__device__ float g_r1[R_ELEMS];
__device__ float g_r2[R_ELEMS];
__device__ float g_im[MAP_ELEMS];
__device__ float g_im1[MAP_ELEMS];
__device__ float g_inc[MAP_ELEMS];
__device__ float g_outmap[MAP_ELEMS];

// ---------------------------------------------------------------------------
// 1) bilinear x2 (align_corners) + sigmoid for both maps.
// ---------------------------------------------------------------------------
__global__ void upsample_sig_kernel(const float* __restrict__ in_map) {
    int idx = blockIdx.x * blockDim.x + threadIdx.x;
    if (idx >= MAP_ELEMS) return;
    int b = idx / (H2 * W2);
    int p = idx % (H2 * W2);
    int oy = p / W2, ox = p % W2;
    float cy = oy * (63.0f / 127.0f);
    float cx = ox * (63.0f / 127.0f);
    int y0 = (int)floorf(cy); int y1 = min(y0 + 1, HH - 1);
    int x0 = (int)floorf(cx); int x1 = min(x0 + 1, WW - 1);
    float wy = cy - (float)y0, wx = cx - (float)x0;
    const float* m = in_map + b * HH * WW;
    float v00 = m[y0 * WW + x0], v01 = m[y0 * WW + x1];
    float v10 = m[y1 * WW + x0], v11 = m[y1 * WW + x1];
    float u = v00 * (1.f - wy) * (1.f - wx) + v01 * (1.f - wy) * wx
            + v10 * wy * (1.f - wx)        + v11 * wy * wx;
    g_im[idx]  = 1.0f / (1.0f + expf(-u));
    g_im1[idx] = 1.0f / (1.0f + expf(-(1.0f - u)));
}

// ---------------------------------------------------------------------------
// 2) inc = dilate3x3(im) - im ; 3) outmap = dilate(inc)+dilate(im1)-im1
// ---------------------------------------------------------------------------
__device__ __forceinline__ float max3x3(const float* m, int oy, int ox) {
    float mx = -3.4e38f;
    #pragma unroll
    for (int dy = -1; dy <= 1; dy++) {
        int y = oy + dy;
        if (y < 0 || y >= H2) continue;
        #pragma unroll
        for (int dx = -1; dx <= 1; dx++) {
            int x = ox + dx;
            if (x < 0 || x >= W2) continue;
            mx = fmaxf(mx, m[y * W2 + x]);
        }
    }
    return mx;
}

__global__ void inc_kernel() {
    int idx = blockIdx.x * blockDim.x + threadIdx.x;
    if (idx >= MAP_ELEMS) return;
    int b = idx / (H2 * W2);
    int p = idx % (H2 * W2);
    int oy = p / W2, ox = p % W2;
    const float* m = g_im + b * H2 * W2;
    g_inc[idx] = max3x3(m, oy, ox) - m[oy * W2 + ox];
}

__global__ void outmap_kernel() {
    int idx = blockIdx.x * blockDim.x + threadIdx.x;
    if (idx >= MAP_ELEMS) return;
    int b = idx / (H2 * W2);
    int p = idx % (H2 * W2);
    int oy = p / W2, ox = p % W2;
    const float* mi = g_inc + b * H2 * W2;
    const float* m1 = g_im1 + b * H2 * W2;
    g_outmap[idx] = max3x3(mi, oy, ox) + max3x3(m1, oy, ox) - m1[oy * W2 + ox];
}

// ---------------------------------------------------------------------------
// 4) up-conv 7x7 (128->256, 64x64) + bias + BN + ReLU + pixel_shuffle -> g_dep
//    Weights staged transposed: sW[tap*8 + o]  ->  2x LDS.128 per tap.
// ---------------------------------------------------------------------------
__global__ __launch_bounds__(256) void up_conv_kernel(
    const float* __restrict__ x, const float* __restrict__ w,
    const float* __restrict__ bias, const float* __restrict__ bn)
{
    __shared__ float sIn[38 * 38];
    __shared__ __align__(16) float sW[49 * 8];
    int tid = threadIdx.x;
    int tx = tid & 15, ty = tid >> 4;
    int bx = blockIdx.x, by = blockIdx.y;
    int b = blockIdx.z >> 5;
    int oc_base = (blockIdx.z & 31) * 8;
    int y0 = by * 32 - 3, x0 = bx * 32 - 3;

    float acc[8][2][2];
    #pragma unroll
    for (int o = 0; o < 8; o++)
        #pragma unroll
        for (int dy = 0; dy < 2; dy++)
            #pragma unroll
            for (int dx = 0; dx < 2; dx++) acc[o][dy][dx] = 0.0f;

    for (int ci = 0; ci < C2; ci++) {
        const float* xin = x + (b * C2 + ci) * HH * WW;
        for (int i = tid; i < 38 * 38; i += 256) {
            int r = i / 38, c = i % 38;
            int gy = y0 + r, gx = x0 + c;
            sIn[i] = (gy >= 0 && gy < HH && gx >= 0 && gx < WW) ? xin[gy * WW + gx] : 0.0f;
        }
        for (int i = tid; i < 49 * 8; i += 256) {
            int o = i & 7, k = i >> 3;
            sW[i] = w[((oc_base + o) * C2 + ci) * 49 + k];
        }
        __syncthreads();
        #pragma unroll 1
        for (int kh = 0; kh < 7; kh++) {
            #pragma unroll
            for (int kw = 0; kw < 7; kw++) {
                int k = kh * 7 + kw;
                float4 wa = *(const float4*)(sW + k * 8);
                float4 wb = *(const float4*)(sW + k * 8 + 4);
                float wv[8] = {wa.x, wa.y, wa.z, wa.w, wb.x, wb.y, wb.z, wb.w};
                #pragma unroll
                for (int dy = 0; dy < 2; dy++)
                    #pragma unroll
                    for (int dx = 0; dx < 2; dx++) {
                        float v = sIn[(ty + dy * 16 + kh) * 38 + (tx + dx * 16 + kw)];
                        #pragma unroll
                        for (int o = 0; o < 8; o++)
                            acc[o][dy][dx] = fmaf(wv[o], v, acc[o][dy][dx]);
                    }
            }
        }
        __syncthreads();
    }

    #pragma unroll
    for (int o = 0; o < 8; o++) {
        int c4 = oc_base + o;
        float gam = bn[c4], bet = bn[256 + c4], mu = bn[512 + c4], var = bn[768 + c4];
        float scale = gam * rsqrtf(var + 1e-5f);
        float off = (bias[c4] - mu) * scale + bet;
        int c = c4 >> 2, a = (c4 >> 1) & 1, d = c4 & 1;
        #pragma unroll
        for (int dy = 0; dy < 2; dy++)
            #pragma unroll
            for (int dx = 0; dx < 2; dx++) {
                int h = by * 32 + ty + dy * 16;
                int ww2 = bx * 32 + tx + dx * 16;
                float v = fmaxf(fmaf(acc[o][dy][dx], scale, off), 0.0f);
                g_dep[((b * C1 + c) * H2 + 2 * h + a) * W2 + 2 * ww2 + d] = v;
            }
    }
}

// ---------------------------------------------------------------------------
// 5) conv2 3x3 (64->64, 128x128) on (outmap * cur_x); t1 = dep + beta*(conv+b)
// ---------------------------------------------------------------------------
__global__ __launch_bounds__(256) void conv2_kernel(
    const float* __restrict__ x, const float* __restrict__ w,
    const float* __restrict__ bias, const float* __restrict__ beta)
{
    __shared__ float sIn[34 * 34];
    __shared__ float sMap[34 * 34];
    __shared__ __align__(16) float sW[9 * 8];
    int tid = threadIdx.x;
    int tx = tid & 15, ty = tid >> 4;
    int bx = blockIdx.x, by = blockIdx.y;
    int b = blockIdx.z >> 3;
    int oc_base = (blockIdx.z & 7) * 8;
    int y0 = by * 32 - 1, x0 = bx * 32 - 1;

    const float* om = g_outmap + b * H2 * W2;
    for (int i = tid; i < 34 * 34; i += 256) {
        int r = i / 34, c = i % 34;
        int gy = y0 + r, gx = x0 + c;
        sMap[i] = (gy >= 0 && gy < H2 && gx >= 0 && gx < W2) ? om[gy * W2 + gx] : 0.0f;
    }
    __syncthreads();

    float acc[8][2][2];
    #pragma unroll
    for (int o = 0; o < 8; o++)
        #pragma unroll
        for (int dy = 0; dy < 2; dy++)
            #pragma unroll
            for (int dx = 0; dx < 2; dx++) acc[o][dy][dx] = 0.0f;

    for (int ci = 0; ci < C1; ci++) {
        const float* xin = x + (b * C1 + ci) * H2 * W2;
        for (int i = tid; i < 34 * 34; i += 256) {
            int r = i / 34, c = i % 34;
            int gy = y0 + r, gx = x0 + c;
            float v = (gy >= 0 && gy < H2 && gx >= 0 && gx < W2) ? xin[gy * W2 + gx] : 0.0f;
            sIn[i] = v * sMap[i];
        }
        for (int i = tid; i < 9 * 8; i += 256) {
            int o = i & 7, k = i >> 3;
            sW[i] = w[((oc_base + o) * C1 + ci) * 9 + k];
        }
        __syncthreads();
        #pragma unroll
        for (int kh = 0; kh < 3; kh++)
            #pragma unroll
            for (int kw = 0; kw < 3; kw++) {
                int k = kh * 3 + kw;
                float4 wa = *(const float4*)(sW + k * 8);
                float4 wb = *(const float4*)(sW + k * 8 + 4);
                float wv[8] = {wa.x, wa.y, wa.z, wa.w, wb.x, wb.y, wb.z, wb.w};
                #pragma unroll
                for (int dy = 0; dy < 2; dy++)
                    #pragma unroll
                    for (int dx = 0; dx < 2; dx++) {
                        float v = sIn[(ty + dy * 16 + kh) * 34 + (tx + dx * 16 + kw)];
                        #pragma unroll
                        for (int o = 0; o < 8; o++)
                            acc[o][dy][dx] = fmaf(wv[o], v, acc[o][dy][dx]);
                    }
            }
        __syncthreads();
    }

    float bt = beta[0];
    #pragma unroll
    for (int o = 0; o < 8; o++) {
        int oc = oc_base + o;
        float bz = bias[oc];
        #pragma unroll
        for (int dy = 0; dy < 2; dy++)
            #pragma unroll
            for (int dx = 0; dx < 2; dx++) {
                int y = by * 32 + ty + dy * 16;
                int xx = bx * 32 + tx + dx * 16;
                int idx = ((b * C1 + oc) * H2 + y) * W2 + xx;
                g_t1[idx] = g_dep[idx] + bt * (acc[o][dy][dx] + bz);
            }
    }
}

// ---------------------------------------------------------------------------
// 6) generic conv3x3 (64->64, 128x128) + bias + BN + ReLU
// ---------------------------------------------------------------------------
__global__ __launch_bounds__(256) void conv3_bn_relu_kernel(
    const float* __restrict__ in, const float* __restrict__ w,
    const float* __restrict__ bias, const float* __restrict__ bn,
    float* __restrict__ out)
{
    __shared__ float sIn[34 * 34];
    __shared__ __align__(16) float sW[9 * 8];
    int tid = threadIdx.x;
    int tx = tid & 15, ty = tid >> 4;
    int bx = blockIdx.x, by = blockIdx.y;
    int b = blockIdx.z >> 3;
    int oc_base = (blockIdx.z & 7) * 8;
    int y0 = by * 32 - 1, x0 = bx * 32 - 1;

    float acc[8][2][2];
    #pragma unroll
    for (int o = 0; o < 8; o++)
        #pragma unroll
        for (int dy = 0; dy < 2; dy++)
            #pragma unroll
            for (int dx = 0; dx < 2; dx++) acc[o][dy][dx] = 0.0f;

    for (int ci = 0; ci < C1; ci++) {
        const float* xin = in + (b * C1 + ci) * H2 * W2;
        for (int i = tid; i < 34 * 34; i += 256) {
            int r = i / 34, c = i % 34;
            int gy = y0 + r, gx = x0 + c;
            sIn[i] = (gy >= 0 && gy < H2 && gx >= 0 && gx < W2) ? xin[gy * W2 + gx] : 0.0f;
        }
        for (int i = tid; i < 9 * 8; i += 256) {
            int o = i & 7, k = i >> 3;
            sW[i] = w[((oc_base + o) * C1 + ci) * 9 + k];
        }
        __syncthreads();
        #pragma unroll
        for (int kh = 0; kh < 3; kh++)
            #pragma unroll
            for (int kw = 0; kw < 3; kw++) {
                int k = kh * 3 + kw;
                float4 wa = *(const float4*)(sW + k * 8);
                float4 wb = *(const float4*)(sW + k * 8 + 4);
                float wv[8] = {wa.x, wa.y, wa.z, wa.w, wb.x, wb.y, wb.z, wb.w};
                #pragma unroll
                for (int dy = 0; dy < 2; dy++)
                    #pragma unroll
                    for (int dx = 0; dx < 2; dx++) {
                        float v = sIn[(ty + dy * 16 + kh) * 34 + (tx + dx * 16 + kw)];
                        #pragma unroll
                        for (int o = 0; o < 8; o++)
                            acc[o][dy][dx] = fmaf(wv[o], v, acc[o][dy][dx]);
                    }
            }
        __syncthreads();
    }

    #pragma unroll
    for (int o = 0; o < 8; o++) {
        int oc = oc_base + o;
        float gam = bn[oc], bet = bn[64 + oc], mu = bn[128 + oc], var = bn[192 + oc];
        float scale = gam * rsqrtf(var + 1e-5f);
        float off = (bias[oc] - mu) * scale + bet;
        #pragma unroll
        for (int dy = 0; dy < 2; dy++)
            #pragma unroll
            for (int dx = 0; dx < 2; dx++) {
                int y = by * 32 + ty + dy * 16;
                int xx = bx * 32 + tx + dx * 16;
                float v = fmaxf(fmaf(acc[o][dy][dx], scale, off), 0.0f);
                out[((b * C1 + oc) * H2 + y) * W2 + xx] = v;
            }
    }
}

// ---------------------------------------------------------------------------
// 7) out-conv 7x7 (64->1, 128x128) + bias
// ---------------------------------------------------------------------------
__global__ __launch_bounds__(256) void out_conv_kernel(
    const float* __restrict__ rin, const float* __restrict__ w,
    const float* __restrict__ bias, float* __restrict__ out)
{
    __shared__ float sIn[22 * 22];
    __shared__ float sW[49];
    int tid = threadIdx.x;
    int tx = tid & 15, ty = tid >> 4;
    int bx = blockIdx.x, by = blockIdx.y;
    int b = blockIdx.z;
    int y0 = by * 16 - 3, x0 = bx * 16 - 3;

    float acc = 0.0f;
    for (int ci = 0; ci < C1; ci++) {
        const float* xin = rin + (b * C1 + ci) * H2 * W2;
        for (int i = tid; i < 22 * 22; i += 256) {
            int r = i / 22, c = i % 22;
            int gy = y0 + r, gx = x0 + c;
            sIn[i] = (gy >= 0 && gy < H2 && gx >= 0 && gx < W2) ? xin[gy * W2 + gx] : 0.0f;
        }
        if (tid < 49) sW[tid] = w[ci * 49 + tid];
        __syncthreads();
        #pragma unroll 1
        for (int kh = 0; kh < 7; kh++)
            #pragma unroll
            for (int kw = 0; kw < 7; kw++)
                acc = fmaf(sIn[(ty + kh) * 22 + (tx + kw)], sW[kh * 7 + kw], acc);
        __syncthreads();
    }
    int y = by * 16 + ty, xx = bx * 16 + tx;
    out[b * H2 * W2 + y * W2 + xx] = acc + bias[0];
}

// ---------------------------------------------------------------------------
extern "C" void kernel_launch(void* const* d_in, const int* in_sizes, int n_in,
                              void* d_out, int out_size) {
    const float* cur_x   = (const float*)d_in[0];
    const float* dep_x   = (const float*)d_in[1];
    const float* in_map  = (const float*)d_in[2];
    const float* up_w    = (const float*)d_in[3];
    const float* up_b    = (const float*)d_in[4];
    const float* up_bn   = (const float*)d_in[5];
    const float* conv2_w = (const float*)d_in[6];
    const float* conv2_b = (const float*)d_in[7];
    const float* d1_w    = (const float*)d_in[8];
    const float* d1_b    = (const float*)d_in[9];
    const float* d1_bn   = (const float*)d_in[10];
    const float* d2_w    = (const float*)d_in[11];
    const float* d2_b    = (const float*)d_in[12];
    const float* d2_bn   = (const float*)d_in[13];
    const float* d3_w    = (const float*)d_in[14];
    const float* d3_b    = (const float*)d_in[15];
    const float* d3_bn   = (const float*)d_in[16];
    const float* out_w   = (const float*)d_in[17];
    const float* out_b   = (const float*)d_in[18];
    const float* beta    = (const float*)d_in[19];
    float* out = (float*)d_out;

    float *p_t1, *p_r1, *p_r2;
    cudaGetSymbolAddress((void**)&p_t1, g_t1);
    cudaGetSymbolAddress((void**)&p_r1, g_r1);
    cudaGetSymbolAddress((void**)&p_r2, g_r2);

    // map pipeline
    upsample_sig_kernel<<<MAP_ELEMS / 256, 256>>>(in_map);
    inc_kernel<<<MAP_ELEMS / 256, 256>>>();
    outmap_kernel<<<MAP_ELEMS / 256, 256>>>();

    // big up-conv + fused BN/ReLU/pixel-shuffle
    up_conv_kernel<<<dim3(2, 2, 256), 256>>>(dep_x, up_w, up_b, up_bn);

    // gated conv2 + residual combine -> t1
    conv2_kernel<<<dim3(4, 4, 64), 256>>>(cur_x, conv2_w, conv2_b, beta);

    // three conv3x3+BN+ReLU stages; last writes r directly into d_out
    conv3_bn_relu_kernel<<<dim3(4, 4, 64), 256>>>(p_t1, d1_w, d1_b, d1_bn, p_r1);
    conv3_bn_relu_kernel<<<dim3(4, 4, 64), 256>>>(p_r1, d2_w, d2_b, d2_bn, p_r2);
    conv3_bn_relu_kernel<<<dim3(4, 4, 64), 256>>>(p_r2, d3_w, d3_b, d3_bn, out);

    // final 7x7 conv -> output_map appended after r
    out_conv_kernel<<<dim3(8, 8, 8), 256>>>(out, out_w, out_b, out + R_ELEMS);
}

// round 4
// speedup vs baseline: 1.3590x; 1.1149x over previous
#include <cuda_runtime.h>
#include <math.h>

#define BB 8
#define C1 64
#define C2 128
#define HH 64
#define WW 64
#define H2 128
#define W2 128

#define R_ELEMS (BB*C1*H2*W2)   /* 8388608 */
#define MAP_ELEMS (BB*H2*W2)    /* 131072  */

__device__ float g_dep[R_ELEMS];
__device__ float g_t1[R_ELEMS];
__device__ float g_r1[R_ELEMS];
__device__ float g_r2[R_ELEMS];
__device__ float g_im[MAP_ELEMS];
__device__ float g_im1[MAP_ELEMS];
__device__ float g_inc[MAP_ELEMS];
__device__ float g_outmap[MAP_ELEMS];

// ---------------------------------------------------------------------------
// 1) bilinear x2 (align_corners) + sigmoid for both maps.
// ---------------------------------------------------------------------------
__global__ void upsample_sig_kernel(const float* __restrict__ in_map) {
    int idx = blockIdx.x * blockDim.x + threadIdx.x;
    if (idx >= MAP_ELEMS) return;
    int b = idx / (H2 * W2);
    int p = idx % (H2 * W2);
    int oy = p / W2, ox = p % W2;
    float cy = oy * (63.0f / 127.0f);
    float cx = ox * (63.0f / 127.0f);
    int y0 = (int)floorf(cy); int y1 = min(y0 + 1, HH - 1);
    int x0 = (int)floorf(cx); int x1 = min(x0 + 1, WW - 1);
    float wy = cy - (float)y0, wx = cx - (float)x0;
    const float* m = in_map + b * HH * WW;
    float v00 = m[y0 * WW + x0], v01 = m[y0 * WW + x1];
    float v10 = m[y1 * WW + x0], v11 = m[y1 * WW + x1];
    float u = v00 * (1.f - wy) * (1.f - wx) + v01 * (1.f - wy) * wx
            + v10 * wy * (1.f - wx)        + v11 * wy * wx;
    g_im[idx]  = 1.0f / (1.0f + expf(-u));
    g_im1[idx] = 1.0f / (1.0f + expf(-(1.0f - u)));
}

// ---------------------------------------------------------------------------
// 2) inc = dilate3x3(im) - im ; 3) outmap = dilate(inc)+dilate(im1)-im1
// ---------------------------------------------------------------------------
__device__ __forceinline__ float max3x3(const float* m, int oy, int ox) {
    float mx = -3.4e38f;
    #pragma unroll
    for (int dy = -1; dy <= 1; dy++) {
        int y = oy + dy;
        if (y < 0 || y >= H2) continue;
        #pragma unroll
        for (int dx = -1; dx <= 1; dx++) {
            int x = ox + dx;
            if (x < 0 || x >= W2) continue;
            mx = fmaxf(mx, m[y * W2 + x]);
        }
    }
    return mx;
}

__global__ void inc_kernel() {
    int idx = blockIdx.x * blockDim.x + threadIdx.x;
    if (idx >= MAP_ELEMS) return;
    int b = idx / (H2 * W2);
    int p = idx % (H2 * W2);
    int oy = p / W2, ox = p % W2;
    const float* m = g_im + b * H2 * W2;
    g_inc[idx] = max3x3(m, oy, ox) - m[oy * W2 + ox];
}

__global__ void outmap_kernel() {
    int idx = blockIdx.x * blockDim.x + threadIdx.x;
    if (idx >= MAP_ELEMS) return;
    int b = idx / (H2 * W2);
    int p = idx % (H2 * W2);
    int oy = p / W2, ox = p % W2;
    const float* mi = g_inc + b * H2 * W2;
    const float* m1 = g_im1 + b * H2 * W2;
    g_outmap[idx] = max3x3(mi, oy, ox) + max3x3(m1, oy, ox) - m1[oy * W2 + ox];
}

// ---------------------------------------------------------------------------
// 4) up-conv 7x7 (128->256, 64x64) + BN + ReLU + pixel_shuffle -> g_dep
//    Thread owns cols {2tx, 2tx+1}, rows {ty, ty+16}. Row strips held in
//    registers and slid across kw -> per-kh: 8 LDS.64 in + 14 LDS.128 w
//    vs 224 FFMA.
// ---------------------------------------------------------------------------
__global__ __launch_bounds__(256) void up_conv_kernel(
    const float* __restrict__ x, const float* __restrict__ w,
    const float* __restrict__ bias, const float* __restrict__ bn)
{
    __shared__ float sIn[38 * 40];
    __shared__ __align__(16) float sW[49 * 8];
    int tid = threadIdx.x;
    int tx = tid & 15, ty = tid >> 4;
    int bx = blockIdx.x, by = blockIdx.y;
    int b = blockIdx.z >> 5;
    int oc_base = (blockIdx.z & 31) * 8;
    int y0 = by * 32 - 3, x0 = bx * 32 - 3;

    float acc[8][2][2];
    #pragma unroll
    for (int o = 0; o < 8; o++)
        #pragma unroll
        for (int dy = 0; dy < 2; dy++)
            #pragma unroll
            for (int dx = 0; dx < 2; dx++) acc[o][dy][dx] = 0.0f;

    for (int ci = 0; ci < C2; ci++) {
        const float* xin = x + (b * C2 + ci) * HH * WW;
        for (int i = tid; i < 38 * 38; i += 256) {
            int r = i / 38, c = i % 38;
            int gy = y0 + r, gx = x0 + c;
            sIn[r * 40 + c] = (gy >= 0 && gy < HH && gx >= 0 && gx < WW) ? xin[gy * WW + gx] : 0.0f;
        }
        for (int i = tid; i < 49 * 8; i += 256) {
            int o = i & 7, k = i >> 3;
            sW[i] = w[((oc_base + o) * C2 + ci) * 49 + k];
        }
        __syncthreads();
        #pragma unroll 1
        for (int kh = 0; kh < 7; kh++) {
            float s[2][8];
            #pragma unroll
            for (int dy = 0; dy < 2; dy++) {
                int row = ty + dy * 16 + kh;
                #pragma unroll
                for (int j = 0; j < 4; j++) {
                    float2 v2 = *(const float2*)(sIn + row * 40 + 2 * tx + 2 * j);
                    s[dy][2 * j] = v2.x;
                    s[dy][2 * j + 1] = v2.y;
                }
            }
            #pragma unroll
            for (int kw = 0; kw < 7; kw++) {
                int k = kh * 7 + kw;
                float4 wa = *(const float4*)(sW + k * 8);
                float4 wb = *(const float4*)(sW + k * 8 + 4);
                float wv[8] = {wa.x, wa.y, wa.z, wa.w, wb.x, wb.y, wb.z, wb.w};
                #pragma unroll
                for (int dy = 0; dy < 2; dy++)
                    #pragma unroll
                    for (int dx = 0; dx < 2; dx++) {
                        float v = s[dy][kw + dx];
                        #pragma unroll
                        for (int o = 0; o < 8; o++)
                            acc[o][dy][dx] = fmaf(wv[o], v, acc[o][dy][dx]);
                    }
            }
        }
        __syncthreads();
    }

    #pragma unroll
    for (int o = 0; o < 8; o++) {
        int c4 = oc_base + o;
        float gam = bn[c4], bet = bn[256 + c4], mu = bn[512 + c4], var = bn[768 + c4];
        float scale = gam * rsqrtf(var + 1e-5f);
        float off = (bias[c4] - mu) * scale + bet;
        int c = c4 >> 2, a = (c4 >> 1) & 1, d = c4 & 1;
        #pragma unroll
        for (int dy = 0; dy < 2; dy++)
            #pragma unroll
            for (int dx = 0; dx < 2; dx++) {
                int h = by * 32 + ty + dy * 16;
                int ww2 = bx * 32 + 2 * tx + dx;
                float v = fmaxf(fmaf(acc[o][dy][dx], scale, off), 0.0f);
                g_dep[((b * C1 + c) * H2 + 2 * h + a) * W2 + 2 * ww2 + d] = v;
            }
    }
}

// ---------------------------------------------------------------------------
// 5) conv2 3x3 (64->64, 128x128) on (outmap * cur_x); t1 = dep + beta*(conv+b)
// ---------------------------------------------------------------------------
__global__ __launch_bounds__(256) void conv2_kernel(
    const float* __restrict__ x, const float* __restrict__ w,
    const float* __restrict__ bias, const float* __restrict__ beta)
{
    __shared__ float sIn[34 * 36];
    __shared__ float sMap[34 * 36];
    __shared__ __align__(16) float sW[9 * 8];
    int tid = threadIdx.x;
    int tx = tid & 15, ty = tid >> 4;
    int bx = blockIdx.x, by = blockIdx.y;
    int b = blockIdx.z >> 3;
    int oc_base = (blockIdx.z & 7) * 8;
    int y0 = by * 32 - 1, x0 = bx * 32 - 1;

    const float* om = g_outmap + b * H2 * W2;
    for (int i = tid; i < 34 * 34; i += 256) {
        int r = i / 34, c = i % 34;
        int gy = y0 + r, gx = x0 + c;
        sMap[r * 36 + c] = (gy >= 0 && gy < H2 && gx >= 0 && gx < W2) ? om[gy * W2 + gx] : 0.0f;
    }
    __syncthreads();

    float acc[8][2][2];
    #pragma unroll
    for (int o = 0; o < 8; o++)
        #pragma unroll
        for (int dy = 0; dy < 2; dy++)
            #pragma unroll
            for (int dx = 0; dx < 2; dx++) acc[o][dy][dx] = 0.0f;

    for (int ci = 0; ci < C1; ci++) {
        const float* xin = x + (b * C1 + ci) * H2 * W2;
        for (int i = tid; i < 34 * 34; i += 256) {
            int r = i / 34, c = i % 34;
            int gy = y0 + r, gx = x0 + c;
            float v = (gy >= 0 && gy < H2 && gx >= 0 && gx < W2) ? xin[gy * W2 + gx] : 0.0f;
            sIn[r * 36 + c] = v * sMap[r * 36 + c];
        }
        for (int i = tid; i < 9 * 8; i += 256) {
            int o = i & 7, k = i >> 3;
            sW[i] = w[((oc_base + o) * C1 + ci) * 9 + k];
        }
        __syncthreads();
        #pragma unroll
        for (int kh = 0; kh < 3; kh++) {
            float s[2][4];
            #pragma unroll
            for (int dy = 0; dy < 2; dy++) {
                int row = ty + dy * 16 + kh;
                #pragma unroll
                for (int j = 0; j < 2; j++) {
                    float2 v2 = *(const float2*)(sIn + row * 36 + 2 * tx + 2 * j);
                    s[dy][2 * j] = v2.x;
                    s[dy][2 * j + 1] = v2.y;
                }
            }
            #pragma unroll
            for (int kw = 0; kw < 3; kw++) {
                int k = kh * 3 + kw;
                float4 wa = *(const float4*)(sW + k * 8);
                float4 wb = *(const float4*)(sW + k * 8 + 4);
                float wv[8] = {wa.x, wa.y, wa.z, wa.w, wb.x, wb.y, wb.z, wb.w};
                #pragma unroll
                for (int dy = 0; dy < 2; dy++)
                    #pragma unroll
                    for (int dx = 0; dx < 2; dx++) {
                        float v = s[dy][kw + dx];
                        #pragma unroll
                        for (int o = 0; o < 8; o++)
                            acc[o][dy][dx] = fmaf(wv[o], v, acc[o][dy][dx]);
                    }
            }
        }
        __syncthreads();
    }

    float bt = beta[0];
    #pragma unroll
    for (int o = 0; o < 8; o++) {
        int oc = oc_base + o;
        float bz = bias[oc];
        #pragma unroll
        for (int dy = 0; dy < 2; dy++)
            #pragma unroll
            for (int dx = 0; dx < 2; dx++) {
                int y = by * 32 + ty + dy * 16;
                int xx = bx * 32 + 2 * tx + dx;
                int idx = ((b * C1 + oc) * H2 + y) * W2 + xx;
                g_t1[idx] = g_dep[idx] + bt * (acc[o][dy][dx] + bz);
            }
    }
}

// ---------------------------------------------------------------------------
// 6) generic conv3x3 (64->64, 128x128) + bias + BN + ReLU
// ---------------------------------------------------------------------------
__global__ __launch_bounds__(256) void conv3_bn_relu_kernel(
    const float* __restrict__ in, const float* __restrict__ w,
    const float* __restrict__ bias, const float* __restrict__ bn,
    float* __restrict__ out)
{
    __shared__ float sIn[34 * 36];
    __shared__ __align__(16) float sW[9 * 8];
    int tid = threadIdx.x;
    int tx = tid & 15, ty = tid >> 4;
    int bx = blockIdx.x, by = blockIdx.y;
    int b = blockIdx.z >> 3;
    int oc_base = (blockIdx.z & 7) * 8;
    int y0 = by * 32 - 1, x0 = bx * 32 - 1;

    float acc[8][2][2];
    #pragma unroll
    for (int o = 0; o < 8; o++)
        #pragma unroll
        for (int dy = 0; dy < 2; dy++)
            #pragma unroll
            for (int dx = 0; dx < 2; dx++) acc[o][dy][dx] = 0.0f;

    for (int ci = 0; ci < C1; ci++) {
        const float* xin = in + (b * C1 + ci) * H2 * W2;
        for (int i = tid; i < 34 * 34; i += 256) {
            int r = i / 34, c = i % 34;
            int gy = y0 + r, gx = x0 + c;
            sIn[r * 36 + c] = (gy >= 0 && gy < H2 && gx >= 0 && gx < W2) ? xin[gy * W2 + gx] : 0.0f;
        }
        for (int i = tid; i < 9 * 8; i += 256) {
            int o = i & 7, k = i >> 3;
            sW[i] = w[((oc_base + o) * C1 + ci) * 9 + k];
        }
        __syncthreads();
        #pragma unroll
        for (int kh = 0; kh < 3; kh++) {
            float s[2][4];
            #pragma unroll
            for (int dy = 0; dy < 2; dy++) {
                int row = ty + dy * 16 + kh;
                #pragma unroll
                for (int j = 0; j < 2; j++) {
                    float2 v2 = *(const float2*)(sIn + row * 36 + 2 * tx + 2 * j);
                    s[dy][2 * j] = v2.x;
                    s[dy][2 * j + 1] = v2.y;
                }
            }
            #pragma unroll
            for (int kw = 0; kw < 3; kw++) {
                int k = kh * 3 + kw;
                float4 wa = *(const float4*)(sW + k * 8);
                float4 wb = *(const float4*)(sW + k * 8 + 4);
                float wv[8] = {wa.x, wa.y, wa.z, wa.w, wb.x, wb.y, wb.z, wb.w};
                #pragma unroll
                for (int dy = 0; dy < 2; dy++)
                    #pragma unroll
                    for (int dx = 0; dx < 2; dx++) {
                        float v = s[dy][kw + dx];
                        #pragma unroll
                        for (int o = 0; o < 8; o++)
                            acc[o][dy][dx] = fmaf(wv[o], v, acc[o][dy][dx]);
                    }
            }
        }
        __syncthreads();
    }

    #pragma unroll
    for (int o = 0; o < 8; o++) {
        int oc = oc_base + o;
        float gam = bn[oc], bet = bn[64 + oc], mu = bn[128 + oc], var = bn[192 + oc];
        float scale = gam * rsqrtf(var + 1e-5f);
        float off = (bias[oc] - mu) * scale + bet;
        #pragma unroll
        for (int dy = 0; dy < 2; dy++) {
            int y = by * 32 + ty + dy * 16;
            int xx = bx * 32 + 2 * tx;
            float2 v2;
            v2.x = fmaxf(fmaf(acc[o][dy][0], scale, off), 0.0f);
            v2.y = fmaxf(fmaf(acc[o][dy][1], scale, off), 0.0f);
            *(float2*)(out + ((b * C1 + oc) * H2 + y) * W2 + xx) = v2;
        }
    }
}

// ---------------------------------------------------------------------------
// 7) out-conv 7x7 (64->1, 128x128) + bias
// ---------------------------------------------------------------------------
__global__ __launch_bounds__(256) void out_conv_kernel(
    const float* __restrict__ rin, const float* __restrict__ w,
    const float* __restrict__ bias, float* __restrict__ out)
{
    __shared__ float sIn[22 * 22];
    __shared__ float sW[49];
    int tid = threadIdx.x;
    int tx = tid & 15, ty = tid >> 4;
    int bx = blockIdx.x, by = blockIdx.y;
    int b = blockIdx.z;
    int y0 = by * 16 - 3, x0 = bx * 16 - 3;

    float acc = 0.0f;
    for (int ci = 0; ci < C1; ci++) {
        const float* xin = rin + (b * C1 + ci) * H2 * W2;
        for (int i = tid; i < 22 * 22; i += 256) {
            int r = i / 22, c = i % 22;
            int gy = y0 + r, gx = x0 + c;
            sIn[i] = (gy >= 0 && gy < H2 && gx >= 0 && gx < W2) ? xin[gy * W2 + gx] : 0.0f;
        }
        if (tid < 49) sW[tid] = w[ci * 49 + tid];
        __syncthreads();
        #pragma unroll 1
        for (int kh = 0; kh < 7; kh++)
            #pragma unroll
            for (int kw = 0; kw < 7; kw++)
                acc = fmaf(sIn[(ty + kh) * 22 + (tx + kw)], sW[kh * 7 + kw], acc);
        __syncthreads();
    }
    int y = by * 16 + ty, xx = bx * 16 + tx;
    out[b * H2 * W2 + y * W2 + xx] = acc + bias[0];
}

// ---------------------------------------------------------------------------
extern "C" void kernel_launch(void* const* d_in, const int* in_sizes, int n_in,
                              void* d_out, int out_size) {
    const float* cur_x   = (const float*)d_in[0];
    const float* dep_x   = (const float*)d_in[1];
    const float* in_map  = (const float*)d_in[2];
    const float* up_w    = (const float*)d_in[3];
    const float* up_b    = (const float*)d_in[4];
    const float* up_bn   = (const float*)d_in[5];
    const float* conv2_w = (const float*)d_in[6];
    const float* conv2_b = (const float*)d_in[7];
    const float* d1_w    = (const float*)d_in[8];
    const float* d1_b    = (const float*)d_in[9];
    const float* d1_bn   = (const float*)d_in[10];
    const float* d2_w    = (const float*)d_in[11];
    const float* d2_b    = (const float*)d_in[12];
    const float* d2_bn   = (const float*)d_in[13];
    const float* d3_w    = (const float*)d_in[14];
    const float* d3_b    = (const float*)d_in[15];
    const float* d3_bn   = (const float*)d_in[16];
    const float* out_w   = (const float*)d_in[17];
    const float* out_b   = (const float*)d_in[18];
    const float* beta    = (const float*)d_in[19];
    float* out = (float*)d_out;

    float *p_t1, *p_r1, *p_r2;
    cudaGetSymbolAddress((void**)&p_t1, g_t1);
    cudaGetSymbolAddress((void**)&p_r1, g_r1);
    cudaGetSymbolAddress((void**)&p_r2, g_r2);

    upsample_sig_kernel<<<MAP_ELEMS / 256, 256>>>(in_map);
    inc_kernel<<<MAP_ELEMS / 256, 256>>>();
    outmap_kernel<<<MAP_ELEMS / 256, 256>>>();

    up_conv_kernel<<<dim3(2, 2, 256), 256>>>(dep_x, up_w, up_b, up_bn);

    conv2_kernel<<<dim3(4, 4, 64), 256>>>(cur_x, conv2_w, conv2_b, beta);

    conv3_bn_relu_kernel<<<dim3(4, 4, 64), 256>>>(p_t1, d1_w, d1_b, d1_bn, p_r1);
    conv3_bn_relu_kernel<<<dim3(4, 4, 64), 256>>>(p_r1, d2_w, d2_b, d2_bn, p_r2);
    conv3_bn_relu_kernel<<<dim3(4, 4, 64), 256>>>(p_r2, d3_w, d3_b, d3_bn, out);

    out_conv_kernel<<<dim3(8, 8, 8), 256>>>(out, out_w, out_b, out + R_ELEMS);
}

// round 6
// speedup vs baseline: 1.3599x; 1.0007x over previous
#include <cuda_runtime.h>
#include <math.h>

#define BB 8
#define C1 64
#define C2 128
#define HH 64
#define WW 64
#define H2 128
#define W2 128

#define R_ELEMS (BB*C1*H2*W2)   /* 8388608 */
#define MAP_ELEMS (BB*H2*W2)    /* 131072  */

__device__ float g_dep[R_ELEMS];
__device__ float g_t1[R_ELEMS];
__device__ float g_r1[R_ELEMS];
__device__ float g_r2[R_ELEMS];
__device__ float g_im[MAP_ELEMS];
__device__ float g_im1[MAP_ELEMS];
__device__ float g_inc[MAP_ELEMS];
__device__ float g_outmap[MAP_ELEMS];

// ---------------------------------------------------------------------------
// 1) bilinear x2 (align_corners) + sigmoid for both maps.
// ---------------------------------------------------------------------------
__global__ void upsample_sig_kernel(const float* __restrict__ in_map) {
    int idx = blockIdx.x * blockDim.x + threadIdx.x;
    if (idx >= MAP_ELEMS) return;
    int b = idx / (H2 * W2);
    int p = idx % (H2 * W2);
    int oy = p / W2, ox = p % W2;
    float cy = oy * (63.0f / 127.0f);
    float cx = ox * (63.0f / 127.0f);
    int y0 = (int)floorf(cy); int y1 = min(y0 + 1, HH - 1);
    int x0 = (int)floorf(cx); int x1 = min(x0 + 1, WW - 1);
    float wy = cy - (float)y0, wx = cx - (float)x0;
    const float* m = in_map + b * HH * WW;
    float v00 = m[y0 * WW + x0], v01 = m[y0 * WW + x1];
    float v10 = m[y1 * WW + x0], v11 = m[y1 * WW + x1];
    float u = v00 * (1.f - wy) * (1.f - wx) + v01 * (1.f - wy) * wx
            + v10 * wy * (1.f - wx)        + v11 * wy * wx;
    g_im[idx]  = 1.0f / (1.0f + expf(-u));
    g_im1[idx] = 1.0f / (1.0f + expf(-(1.0f - u)));
}

// ---------------------------------------------------------------------------
// 2) inc = dilate3x3(im) - im ; 3) outmap = dilate(inc)+dilate(im1)-im1
// ---------------------------------------------------------------------------
__device__ __forceinline__ float max3x3(const float* m, int oy, int ox) {
    float mx = -3.4e38f;
    #pragma unroll
    for (int dy = -1; dy <= 1; dy++) {
        int y = oy + dy;
        if (y < 0 || y >= H2) continue;
        #pragma unroll
        for (int dx = -1; dx <= 1; dx++) {
            int x = ox + dx;
            if (x < 0 || x >= W2) continue;
            mx = fmaxf(mx, m[y * W2 + x]);
        }
    }
    return mx;
}

__global__ void inc_kernel() {
    int idx = blockIdx.x * blockDim.x + threadIdx.x;
    if (idx >= MAP_ELEMS) return;
    int b = idx / (H2 * W2);
    int p = idx % (H2 * W2);
    int oy = p / W2, ox = p % W2;
    const float* m = g_im + b * H2 * W2;
    g_inc[idx] = max3x3(m, oy, ox) - m[oy * W2 + ox];
}

__global__ void outmap_kernel() {
    int idx = blockIdx.x * blockDim.x + threadIdx.x;
    if (idx >= MAP_ELEMS) return;
    int b = idx / (H2 * W2);
    int p = idx % (H2 * W2);
    int oy = p / W2, ox = p % W2;
    const float* mi = g_inc + b * H2 * W2;
    const float* m1 = g_im1 + b * H2 * W2;
    g_outmap[idx] = max3x3(mi, oy, ox) + max3x3(m1, oy, ox) - m1[oy * W2 + ox];
}

// ---------------------------------------------------------------------------
// 4) up-conv 7x7 (128->256, 64x64) + BN + ReLU + pixel_shuffle -> g_dep
//    Thread owns cols {2tx, 2tx+1}, rows {ty, ty+16}. Row strips held in
//    registers and slid across kw -> per-kh: 8 LDS.64 in + 14 LDS.128 w
//    vs 224 FFMA.
// ---------------------------------------------------------------------------
__global__ __launch_bounds__(256) void up_conv_kernel(
    const float* __restrict__ x, const float* __restrict__ w,
    const float* __restrict__ bias, const float* __restrict__ bn)
{
    __shared__ float sIn[38 * 40];
    __shared__ __align__(16) float sW[49 * 8];
    int tid = threadIdx.x;
    int tx = tid & 15, ty = tid >> 4;
    int bx = blockIdx.x, by = blockIdx.y;
    int b = blockIdx.z >> 5;
    int oc_base = (blockIdx.z & 31) * 8;
    int y0 = by * 32 - 3, x0 = bx * 32 - 3;

    float acc[8][2][2];
    #pragma unroll
    for (int o = 0; o < 8; o++)
        #pragma unroll
        for (int dy = 0; dy < 2; dy++)
            #pragma unroll
            for (int dx = 0; dx < 2; dx++) acc[o][dy][dx] = 0.0f;

    for (int ci = 0; ci < C2; ci++) {
        const float* xin = x + (b * C2 + ci) * HH * WW;
        for (int i = tid; i < 38 * 38; i += 256) {
            int r = i / 38, c = i % 38;
            int gy = y0 + r, gx = x0 + c;
            sIn[r * 40 + c] = (gy >= 0 && gy < HH && gx >= 0 && gx < WW) ? xin[gy * WW + gx] : 0.0f;
        }
        for (int i = tid; i < 49 * 8; i += 256) {
            int o = i & 7, k = i >> 3;
            sW[i] = w[((oc_base + o) * C2 + ci) * 49 + k];
        }
        __syncthreads();
        #pragma unroll 1
        for (int kh = 0; kh < 7; kh++) {
            float s[2][8];
            #pragma unroll
            for (int dy = 0; dy < 2; dy++) {
                int row = ty + dy * 16 + kh;
                #pragma unroll
                for (int j = 0; j < 4; j++) {
                    float2 v2 = *(const float2*)(sIn + row * 40 + 2 * tx + 2 * j);
                    s[dy][2 * j] = v2.x;
                    s[dy][2 * j + 1] = v2.y;
                }
            }
            #pragma unroll
            for (int kw = 0; kw < 7; kw++) {
                int k = kh * 7 + kw;
                float4 wa = *(const float4*)(sW + k * 8);
                float4 wb = *(const float4*)(sW + k * 8 + 4);
                float wv[8] = {wa.x, wa.y, wa.z, wa.w, wb.x, wb.y, wb.z, wb.w};
                #pragma unroll
                for (int dy = 0; dy < 2; dy++)
                    #pragma unroll
                    for (int dx = 0; dx < 2; dx++) {
                        float v = s[dy][kw + dx];
                        #pragma unroll
                        for (int o = 0; o < 8; o++)
                            acc[o][dy][dx] = fmaf(wv[o], v, acc[o][dy][dx]);
                    }
            }
        }
        __syncthreads();
    }

    #pragma unroll
    for (int o = 0; o < 8; o++) {
        int c4 = oc_base + o;
        float gam = bn[c4], bet = bn[256 + c4], mu = bn[512 + c4], var = bn[768 + c4];
        float scale = gam * rsqrtf(var + 1e-5f);
        float off = (bias[c4] - mu) * scale + bet;
        int c = c4 >> 2, a = (c4 >> 1) & 1, d = c4 & 1;
        #pragma unroll
        for (int dy = 0; dy < 2; dy++)
            #pragma unroll
            for (int dx = 0; dx < 2; dx++) {
                int h = by * 32 + ty + dy * 16;
                int ww2 = bx * 32 + 2 * tx + dx;
                float v = fmaxf(fmaf(acc[o][dy][dx], scale, off), 0.0f);
                g_dep[((b * C1 + c) * H2 + 2 * h + a) * W2 + 2 * ww2 + d] = v;
            }
    }
}

// ---------------------------------------------------------------------------
// 5) conv2 3x3 (64->64, 128x128) on (outmap * cur_x); t1 = dep + beta*(conv+b)
// ---------------------------------------------------------------------------
__global__ __launch_bounds__(256) void conv2_kernel(
    const float* __restrict__ x, const float* __restrict__ w,
    const float* __restrict__ bias, const float* __restrict__ beta)
{
    __shared__ float sIn[34 * 36];
    __shared__ float sMap[34 * 36];
    __shared__ __align__(16) float sW[9 * 8];
    int tid = threadIdx.x;
    int tx = tid & 15, ty = tid >> 4;
    int bx = blockIdx.x, by = blockIdx.y;
    int b = blockIdx.z >> 3;
    int oc_base = (blockIdx.z & 7) * 8;
    int y0 = by * 32 - 1, x0 = bx * 32 - 1;

    const float* om = g_outmap + b * H2 * W2;
    for (int i = tid; i < 34 * 34; i += 256) {
        int r = i / 34, c = i % 34;
        int gy = y0 + r, gx = x0 + c;
        sMap[r * 36 + c] = (gy >= 0 && gy < H2 && gx >= 0 && gx < W2) ? om[gy * W2 + gx] : 0.0f;
    }
    __syncthreads();

    float acc[8][2][2];
    #pragma unroll
    for (int o = 0; o < 8; o++)
        #pragma unroll
        for (int dy = 0; dy < 2; dy++)
            #pragma unroll
            for (int dx = 0; dx < 2; dx++) acc[o][dy][dx] = 0.0f;

    for (int ci = 0; ci < C1; ci++) {
        const float* xin = x + (b * C1 + ci) * H2 * W2;
        for (int i = tid; i < 34 * 34; i += 256) {
            int r = i / 34, c = i % 34;
            int gy = y0 + r, gx = x0 + c;
            float v = (gy >= 0 && gy < H2 && gx >= 0 && gx < W2) ? xin[gy * W2 + gx] : 0.0f;
            sIn[r * 36 + c] = v * sMap[r * 36 + c];
        }
        for (int i = tid; i < 9 * 8; i += 256) {
            int o = i & 7, k = i >> 3;
            sW[i] = w[((oc_base + o) * C1 + ci) * 9 + k];
        }
        __syncthreads();
        #pragma unroll
        for (int kh = 0; kh < 3; kh++) {
            float s[2][4];
            #pragma unroll
            for (int dy = 0; dy < 2; dy++) {
                int row = ty + dy * 16 + kh;
                #pragma unroll
                for (int j = 0; j < 2; j++) {
                    float2 v2 = *(const float2*)(sIn + row * 36 + 2 * tx + 2 * j);
                    s[dy][2 * j] = v2.x;
                    s[dy][2 * j + 1] = v2.y;
                }
            }
            #pragma unroll
            for (int kw = 0; kw < 3; kw++) {
                int k = kh * 3 + kw;
                float4 wa = *(const float4*)(sW + k * 8);
                float4 wb = *(const float4*)(sW + k * 8 + 4);
                float wv[8] = {wa.x, wa.y, wa.z, wa.w, wb.x, wb.y, wb.z, wb.w};
                #pragma unroll
                for (int dy = 0; dy < 2; dy++)
                    #pragma unroll
                    for (int dx = 0; dx < 2; dx++) {
                        float v = s[dy][kw + dx];
                        #pragma unroll
                        for (int o = 0; o < 8; o++)
                            acc[o][dy][dx] = fmaf(wv[o], v, acc[o][dy][dx]);
                    }
            }
        }
        __syncthreads();
    }

    float bt = beta[0];
    #pragma unroll
    for (int o = 0; o < 8; o++) {
        int oc = oc_base + o;
        float bz = bias[oc];
        #pragma unroll
        for (int dy = 0; dy < 2; dy++)
            #pragma unroll
            for (int dx = 0; dx < 2; dx++) {
                int y = by * 32 + ty + dy * 16;
                int xx = bx * 32 + 2 * tx + dx;
                int idx = ((b * C1 + oc) * H2 + y) * W2 + xx;
                g_t1[idx] = g_dep[idx] + bt * (acc[o][dy][dx] + bz);
            }
    }
}

// ---------------------------------------------------------------------------
// 6) generic conv3x3 (64->64, 128x128) + bias + BN + ReLU
// ---------------------------------------------------------------------------
__global__ __launch_bounds__(256) void conv3_bn_relu_kernel(
    const float* __restrict__ in, const float* __restrict__ w,
    const float* __restrict__ bias, const float* __restrict__ bn,
    float* __restrict__ out)
{
    __shared__ float sIn[34 * 36];
    __shared__ __align__(16) float sW[9 * 8];
    int tid = threadIdx.x;
    int tx = tid & 15, ty = tid >> 4;
    int bx = blockIdx.x, by = blockIdx.y;
    int b = blockIdx.z >> 3;
    int oc_base = (blockIdx.z & 7) * 8;
    int y0 = by * 32 - 1, x0 = bx * 32 - 1;

    float acc[8][2][2];
    #pragma unroll
    for (int o = 0; o < 8; o++)
        #pragma unroll
        for (int dy = 0; dy < 2; dy++)
            #pragma unroll
            for (int dx = 0; dx < 2; dx++) acc[o][dy][dx] = 0.0f;

    for (int ci = 0; ci < C1; ci++) {
        const float* xin = in + (b * C1 + ci) * H2 * W2;
        for (int i = tid; i < 34 * 34; i += 256) {
            int r = i / 34, c = i % 34;
            int gy = y0 + r, gx = x0 + c;
            sIn[r * 36 + c] = (gy >= 0 && gy < H2 && gx >= 0 && gx < W2) ? xin[gy * W2 + gx] : 0.0f;
        }
        for (int i = tid; i < 9 * 8; i += 256) {
            int o = i & 7, k = i >> 3;
            sW[i] = w[((oc_base + o) * C1 + ci) * 9 + k];
        }
        __syncthreads();
        #pragma unroll
        for (int kh = 0; kh < 3; kh++) {
            float s[2][4];
            #pragma unroll
            for (int dy = 0; dy < 2; dy++) {
                int row = ty + dy * 16 + kh;
                #pragma unroll
                for (int j = 0; j < 2; j++) {
                    float2 v2 = *(const float2*)(sIn + row * 36 + 2 * tx + 2 * j);
                    s[dy][2 * j] = v2.x;
                    s[dy][2 * j + 1] = v2.y;
                }
            }
            #pragma unroll
            for (int kw = 0; kw < 3; kw++) {
                int k = kh * 3 + kw;
                float4 wa = *(const float4*)(sW + k * 8);
                float4 wb = *(const float4*)(sW + k * 8 + 4);
                float wv[8] = {wa.x, wa.y, wa.z, wa.w, wb.x, wb.y, wb.z, wb.w};
                #pragma unroll
                for (int dy = 0; dy < 2; dy++)
                    #pragma unroll
                    for (int dx = 0; dx < 2; dx++) {
                        float v = s[dy][kw + dx];
                        #pragma unroll
                        for (int o = 0; o < 8; o++)
                            acc[o][dy][dx] = fmaf(wv[o], v, acc[o][dy][dx]);
                    }
            }
        }
        __syncthreads();
    }

    #pragma unroll
    for (int o = 0; o < 8; o++) {
        int oc = oc_base + o;
        float gam = bn[oc], bet = bn[64 + oc], mu = bn[128 + oc], var = bn[192 + oc];
        float scale = gam * rsqrtf(var + 1e-5f);
        float off = (bias[oc] - mu) * scale + bet;
        #pragma unroll
        for (int dy = 0; dy < 2; dy++) {
            int y = by * 32 + ty + dy * 16;
            int xx = bx * 32 + 2 * tx;
            float2 v2;
            v2.x = fmaxf(fmaf(acc[o][dy][0], scale, off), 0.0f);
            v2.y = fmaxf(fmaf(acc[o][dy][1], scale, off), 0.0f);
            *(float2*)(out + ((b * C1 + oc) * H2 + y) * W2 + xx) = v2;
        }
    }
}

// ---------------------------------------------------------------------------
// 7) out-conv 7x7 (64->1, 128x128) + bias
// ---------------------------------------------------------------------------
__global__ __launch_bounds__(256) void out_conv_kernel(
    const float* __restrict__ rin, const float* __restrict__ w,
    const float* __restrict__ bias, float* __restrict__ out)
{
    __shared__ float sIn[22 * 22];
    __shared__ float sW[49];
    int tid = threadIdx.x;
    int tx = tid & 15, ty = tid >> 4;
    int bx = blockIdx.x, by = blockIdx.y;
    int b = blockIdx.z;
    int y0 = by * 16 - 3, x0 = bx * 16 - 3;

    float acc = 0.0f;
    for (int ci = 0; ci < C1; ci++) {
        const float* xin = rin + (b * C1 + ci) * H2 * W2;
        for (int i = tid; i < 22 * 22; i += 256) {
            int r = i / 22, c = i % 22;
            int gy = y0 + r, gx = x0 + c;
            sIn[i] = (gy >= 0 && gy < H2 && gx >= 0 && gx < W2) ? xin[gy * W2 + gx] : 0.0f;
        }
        if (tid < 49) sW[tid] = w[ci * 49 + tid];
        __syncthreads();
        #pragma unroll 1
        for (int kh = 0; kh < 7; kh++)
            #pragma unroll
            for (int kw = 0; kw < 7; kw++)
                acc = fmaf(sIn[(ty + kh) * 22 + (tx + kw)], sW[kh * 7 + kw], acc);
        __syncthreads();
    }
    int y = by * 16 + ty, xx = bx * 16 + tx;
    out[b * H2 * W2 + y * W2 + xx] = acc + bias[0];
}

// ---------------------------------------------------------------------------
extern "C" void kernel_launch(void* const* d_in, const int* in_sizes, int n_in,
                              void* d_out, int out_size) {
    const float* cur_x   = (const float*)d_in[0];
    const float* dep_x   = (const float*)d_in[1];
    const float* in_map  = (const float*)d_in[2];
    const float* up_w    = (const float*)d_in[3];
    const float* up_b    = (const float*)d_in[4];
    const float* up_bn   = (const float*)d_in[5];
    const float* conv2_w = (const float*)d_in[6];
    const float* conv2_b = (const float*)d_in[7];
    const float* d1_w    = (const float*)d_in[8];
    const float* d1_b    = (const float*)d_in[9];
    const float* d1_bn   = (const float*)d_in[10];
    const float* d2_w    = (const float*)d_in[11];
    const float* d2_b    = (const float*)d_in[12];
    const float* d2_bn   = (const float*)d_in[13];
    const float* d3_w    = (const float*)d_in[14];
    const float* d3_b    = (const float*)d_in[15];
    const float* d3_bn   = (const float*)d_in[16];
    const float* out_w   = (const float*)d_in[17];
    const float* out_b   = (const float*)d_in[18];
    const float* beta    = (const float*)d_in[19];
    float* out = (float*)d_out;

    float *p_t1, *p_r1, *p_r2;
    cudaGetSymbolAddress((void**)&p_t1, g_t1);
    cudaGetSymbolAddress((void**)&p_r1, g_r1);
    cudaGetSymbolAddress((void**)&p_r2, g_r2);

    upsample_sig_kernel<<<MAP_ELEMS / 256, 256>>>(in_map);
    inc_kernel<<<MAP_ELEMS / 256, 256>>>();
    outmap_kernel<<<MAP_ELEMS / 256, 256>>>();

    up_conv_kernel<<<dim3(2, 2, 256), 256>>>(dep_x, up_w, up_b, up_bn);

    conv2_kernel<<<dim3(4, 4, 64), 256>>>(cur_x, conv2_w, conv2_b, beta);

    conv3_bn_relu_kernel<<<dim3(4, 4, 64), 256>>>(p_t1, d1_w, d1_b, d1_bn, p_r1);
    conv3_bn_relu_kernel<<<dim3(4, 4, 64), 256>>>(p_r1, d2_w, d2_b, d2_bn, p_r2);
    conv3_bn_relu_kernel<<<dim3(4, 4, 64), 256>>>(p_r2, d3_w, d3_b, d3_bn, out);

    out_conv_kernel<<<dim3(8, 8, 8), 256>>>(out, out_w, out_b, out + R_ELEMS);
}

// round 9
// speedup vs baseline: 1.4042x; 1.0326x over previous
#include <cuda_runtime.h>
#include <math.h>
#include <stdint.h>

#define BB 8
#define C1 64
#define C2 128
#define HH 64
#define WW 64
#define H2 128
#define W2 128

#define R_ELEMS (BB*C1*H2*W2)   /* 8388608 */
#define MAP_ELEMS (BB*H2*W2)    /* 131072  */

__device__ float g_dep[R_ELEMS];
__device__ float g_t1[R_ELEMS];
__device__ float g_r1[R_ELEMS];
__device__ float g_r2[R_ELEMS];
__device__ float g_im[MAP_ELEMS];
__device__ float g_im1[MAP_ELEMS];
__device__ float g_inc[MAP_ELEMS];
__device__ float g_outmap[MAP_ELEMS];

// ---------------- f32x2 packed-FMA helpers (Blackwell baseline) ----------------
__device__ __forceinline__ uint64_t f2pk(float lo, float hi) {
    uint64_t r;
    asm("mov.b64 %0, {%1, %2};" : "=l"(r) : "f"(lo), "f"(hi));
    return r;
}
__device__ __forceinline__ void ffma2(uint64_t& d, uint64_t a, uint64_t b) {
    asm("fma.rn.f32x2 %0, %1, %2, %0;" : "+l"(d) : "l"(a), "l"(b));
}
__device__ __forceinline__ float2 f2un(uint64_t v) {
    float2 r;
    asm("mov.b64 {%0, %1}, %2;" : "=f"(r.x), "=f"(r.y) : "l"(v));
    return r;
}

// ---------------------------------------------------------------------------
// 1) bilinear x2 (align_corners) + sigmoid for both maps.
// ---------------------------------------------------------------------------
__global__ void upsample_sig_kernel(const float* __restrict__ in_map) {
    int idx = blockIdx.x * blockDim.x + threadIdx.x;
    if (idx >= MAP_ELEMS) return;
    int b = idx / (H2 * W2), p = idx % (H2 * W2);
    int oy = p / W2, ox = p % W2;
    float cy = oy * (63.0f / 127.0f), cx = ox * (63.0f / 127.0f);
    int y0 = (int)floorf(cy); int y1 = min(y0 + 1, HH - 1);
    int x0 = (int)floorf(cx); int x1 = min(x0 + 1, WW - 1);
    float wy = cy - y0, wx = cx - x0;
    const float* m = in_map + b * HH * WW;
    float u = m[y0 * WW + x0] * (1.f - wy) * (1.f - wx) + m[y0 * WW + x1] * (1.f - wy) * wx
            + m[y1 * WW + x0] * wy * (1.f - wx)         + m[y1 * WW + x1] * wy * wx;
    g_im[idx]  = 1.0f / (1.0f + expf(-u));
    g_im1[idx] = 1.0f / (1.0f + expf(-(1.0f - u)));
}

// ---------------------------------------------------------------------------
// 2) inc = dilate3x3(im) - im ; 3) outmap = dilate(inc)+dilate(im1)-im1
// ---------------------------------------------------------------------------
__device__ __forceinline__ float max3x3(const float* m, int oy, int ox) {
    float mx = -3.4e38f;
    #pragma unroll
    for (int dy = -1; dy <= 1; dy++) {
        int y = oy + dy;
        if (y < 0 || y >= H2) continue;
        #pragma unroll
        for (int dx = -1; dx <= 1; dx++) {
            int x = ox + dx;
            if (x < 0 || x >= W2) continue;
            mx = fmaxf(mx, m[y * W2 + x]);
        }
    }
    return mx;
}

__global__ void inc_kernel() {
    int idx = blockIdx.x * blockDim.x + threadIdx.x;
    if (idx >= MAP_ELEMS) return;
    int b = idx / (H2 * W2), p = idx % (H2 * W2);
    const float* m = g_im + b * H2 * W2;
    g_inc[idx] = max3x3(m, p / W2, p % W2) - m[p];
}

__global__ void outmap_kernel() {
    int idx = blockIdx.x * blockDim.x + threadIdx.x;
    if (idx >= MAP_ELEMS) return;
    int b = idx / (H2 * W2), p = idx % (H2 * W2);
    const float* mi = g_inc + b * H2 * W2;
    const float* m1 = g_im1 + b * H2 * W2;
    g_outmap[idx] = max3x3(mi, p / W2, p % W2) + max3x3(m1, p / W2, p % W2) - m1[p];
}

// ---------------------------------------------------------------------------
// 4) up-conv 7x7 (128->256, 64x64) + BN + ReLU + pixel_shuffle -> g_dep
//    f32x2 packed FMAs: acc paired over adjacent oc; weight pairs come
//    directly from LDS.128 of the [tap][8 oc] tile (zero repack cost).
// ---------------------------------------------------------------------------
__global__ __launch_bounds__(256) void up_conv_kernel(
    const float* __restrict__ x, const float* __restrict__ w,
    const float* __restrict__ bias, const float* __restrict__ bn)
{
    __shared__ float sIn[38 * 40];
    __shared__ __align__(16) float sW[49 * 8];
    int tid = threadIdx.x;
    int tx = tid & 15, ty = tid >> 4;
    int bx = blockIdx.x, by = blockIdx.y;
    int b = blockIdx.z >> 5;
    int oc_base = (blockIdx.z & 31) * 8;
    int y0 = by * 32 - 3, x0 = bx * 32 - 3;

    uint64_t acc2[4][2][2];
    #pragma unroll
    for (int p = 0; p < 4; p++)
        #pragma unroll
        for (int dy = 0; dy < 2; dy++)
            #pragma unroll
            for (int dx = 0; dx < 2; dx++) acc2[p][dy][dx] = 0ull;

    for (int ci = 0; ci < C2; ci++) {
        const float* xin = x + (b * C2 + ci) * HH * WW;
        for (int i = tid; i < 38 * 38; i += 256) {
            int r = i / 38, c = i % 38;
            int gy = y0 + r, gx = x0 + c;
            sIn[r * 40 + c] = (gy >= 0 && gy < HH && gx >= 0 && gx < WW) ? xin[gy * WW + gx] : 0.0f;
        }
        for (int i = tid; i < 49 * 8; i += 256) {
            int o = i & 7, k = i >> 3;
            sW[i] = w[((oc_base + o) * C2 + ci) * 49 + k];
        }
        __syncthreads();
        #pragma unroll 1
        for (int kh = 0; kh < 7; kh++) {
            float s[2][8];
            #pragma unroll
            for (int dy = 0; dy < 2; dy++) {
                int row = ty + dy * 16 + kh;
                #pragma unroll
                for (int j = 0; j < 4; j++) {
                    float2 v2 = *(const float2*)(sIn + row * 40 + 2 * tx + 2 * j);
                    s[dy][2 * j] = v2.x;
                    s[dy][2 * j + 1] = v2.y;
                }
            }
            #pragma unroll
            for (int kw = 0; kw < 7; kw++) {
                int k = kh * 7 + kw;
                ulonglong2 wA = *(const ulonglong2*)(sW + k * 8);
                ulonglong2 wB = *(const ulonglong2*)(sW + k * 8 + 4);
                #pragma unroll
                for (int dy = 0; dy < 2; dy++)
                    #pragma unroll
                    for (int dx = 0; dx < 2; dx++) {
                        float v = s[dy][kw + dx];
                        uint64_t vv = f2pk(v, v);
                        ffma2(acc2[0][dy][dx], vv, wA.x);
                        ffma2(acc2[1][dy][dx], vv, wA.y);
                        ffma2(acc2[2][dy][dx], vv, wB.x);
                        ffma2(acc2[3][dy][dx], vv, wB.y);
                    }
            }
        }
        __syncthreads();
    }

    float acc[8][2][2];
    #pragma unroll
    for (int p = 0; p < 4; p++)
        #pragma unroll
        for (int dy = 0; dy < 2; dy++)
            #pragma unroll
            for (int dx = 0; dx < 2; dx++) {
                float2 t = f2un(acc2[p][dy][dx]);
                acc[2 * p][dy][dx] = t.x;
                acc[2 * p + 1][dy][dx] = t.y;
            }

    #pragma unroll
    for (int o = 0; o < 8; o++) {
        int c4 = oc_base + o;
        float gam = bn[c4], bet = bn[256 + c4], mu = bn[512 + c4], var = bn[768 + c4];
        float scale = gam * rsqrtf(var + 1e-5f);
        float off = (bias[c4] - mu) * scale + bet;
        int c = c4 >> 2, a = (c4 >> 1) & 1, d = c4 & 1;
        #pragma unroll
        for (int dy = 0; dy < 2; dy++)
            #pragma unroll
            for (int dx = 0; dx < 2; dx++) {
                int h = by * 32 + ty + dy * 16;
                int ww2 = bx * 32 + 2 * tx + dx;
                float v = fmaxf(fmaf(acc[o][dy][dx], scale, off), 0.0f);
                g_dep[((b * C1 + c) * H2 + 2 * h + a) * W2 + 2 * ww2 + d] = v;
            }
    }
}

// ---------------------------------------------------------------------------
// 5) conv2 3x3 (64->64, 128x128) on (outmap * cur_x); t1 = dep + beta*(conv+b)
// ---------------------------------------------------------------------------
__global__ __launch_bounds__(256) void conv2_kernel(
    const float* __restrict__ x, const float* __restrict__ w,
    const float* __restrict__ bias, const float* __restrict__ beta)
{
    __shared__ float sIn[34 * 36];
    __shared__ float sMap[34 * 36];
    __shared__ __align__(16) float sW[9 * 8];
    int tid = threadIdx.x, tx = tid & 15, ty = tid >> 4;
    int bx = blockIdx.x, by = blockIdx.y;
    int b = blockIdx.z >> 3, oc_base = (blockIdx.z & 7) * 8;
    int y0 = by * 32 - 1, x0 = bx * 32 - 1;

    const float* om = g_outmap + b * H2 * W2;
    for (int i = tid; i < 34 * 34; i += 256) {
        int r = i / 34, c = i % 34, gy = y0 + r, gx = x0 + c;
        sMap[r * 36 + c] = (gy >= 0 && gy < H2 && gx >= 0 && gx < W2) ? om[gy * W2 + gx] : 0.0f;
    }
    __syncthreads();

    uint64_t acc2[4][2][2];
    #pragma unroll
    for (int p = 0; p < 4; p++)
        #pragma unroll
        for (int dy = 0; dy < 2; dy++)
            #pragma unroll
            for (int dx = 0; dx < 2; dx++) acc2[p][dy][dx] = 0ull;

    for (int ci = 0; ci < C1; ci++) {
        const float* xin = x + (b * C1 + ci) * H2 * W2;
        for (int i = tid; i < 34 * 34; i += 256) {
            int r = i / 34, c = i % 34, gy = y0 + r, gx = x0 + c;
            float v = (gy >= 0 && gy < H2 && gx >= 0 && gx < W2) ? xin[gy * W2 + gx] : 0.0f;
            sIn[r * 36 + c] = v * sMap[r * 36 + c];
        }
        for (int i = tid; i < 72; i += 256)
            sW[i] = w[((oc_base + (i & 7)) * C1 + ci) * 9 + (i >> 3)];
        __syncthreads();
        #pragma unroll
        for (int kh = 0; kh < 3; kh++) {
            float s[2][4];
            #pragma unroll
            for (int dy = 0; dy < 2; dy++) {
                int row = ty + dy * 16 + kh;
                #pragma unroll
                for (int j = 0; j < 2; j++) {
                    float2 v2 = *(const float2*)(sIn + row * 36 + 2 * tx + 2 * j);
                    s[dy][2 * j] = v2.x; s[dy][2 * j + 1] = v2.y;
                }
            }
            #pragma unroll
            for (int kw = 0; kw < 3; kw++) {
                int k = kh * 3 + kw;
                ulonglong2 wA = *(const ulonglong2*)(sW + k * 8);
                ulonglong2 wB = *(const ulonglong2*)(sW + k * 8 + 4);
                #pragma unroll
                for (int dy = 0; dy < 2; dy++)
                    #pragma unroll
                    for (int dx = 0; dx < 2; dx++) {
                        float v = s[dy][kw + dx];
                        uint64_t vv = f2pk(v, v);
                        ffma2(acc2[0][dy][dx], vv, wA.x);
                        ffma2(acc2[1][dy][dx], vv, wA.y);
                        ffma2(acc2[2][dy][dx], vv, wB.x);
                        ffma2(acc2[3][dy][dx], vv, wB.y);
                    }
            }
        }
        __syncthreads();
    }

    float bt = beta[0];
    #pragma unroll
    for (int p = 0; p < 4; p++) {
        #pragma unroll
        for (int dy = 0; dy < 2; dy++)
            #pragma unroll
            for (int dx = 0; dx < 2; dx++) {
                float2 t = f2un(acc2[p][dy][dx]);
                int y = by * 32 + ty + dy * 16, xx = bx * 32 + 2 * tx + dx;
                int oc0 = oc_base + 2 * p;
                int i0 = ((b * C1 + oc0) * H2 + y) * W2 + xx;
                int i1 = i0 + H2 * W2;
                g_t1[i0] = g_dep[i0] + bt * (t.x + bias[oc0]);
                g_t1[i1] = g_dep[i1] + bt * (t.y + bias[oc0 + 1]);
            }
    }
}

// ---------------------------------------------------------------------------
// 6) generic conv3x3 (64->64, 128x128) + bias + BN + ReLU
// ---------------------------------------------------------------------------
__global__ __launch_bounds__(256) void conv3_bn_relu_kernel(
    const float* __restrict__ in, const float* __restrict__ w,
    const float* __restrict__ bias, const float* __restrict__ bn,
    float* __restrict__ out)
{
    __shared__ float sIn[34 * 36];
    __shared__ __align__(16) float sW[9 * 8];
    int tid = threadIdx.x, tx = tid & 15, ty = tid >> 4;
    int bx = blockIdx.x, by = blockIdx.y;
    int b = blockIdx.z >> 3, oc_base = (blockIdx.z & 7) * 8;
    int y0 = by * 32 - 1, x0 = bx * 32 - 1;

    uint64_t acc2[4][2][2];
    #pragma unroll
    for (int p = 0; p < 4; p++)
        #pragma unroll
        for (int dy = 0; dy < 2; dy++)
            #pragma unroll
            for (int dx = 0; dx < 2; dx++) acc2[p][dy][dx] = 0ull;

    for (int ci = 0; ci < C1; ci++) {
        const float* xin = in + (b * C1 + ci) * H2 * W2;
        for (int i = tid; i < 34 * 34; i += 256) {
            int r = i / 34, c = i % 34, gy = y0 + r, gx = x0 + c;
            sIn[r * 36 + c] = (gy >= 0 && gy < H2 && gx >= 0 && gx < W2) ? xin[gy * W2 + gx] : 0.0f;
        }
        for (int i = tid; i < 72; i += 256)
            sW[i] = w[((oc_base + (i & 7)) * C1 + ci) * 9 + (i >> 3)];
        __syncthreads();
        #pragma unroll
        for (int kh = 0; kh < 3; kh++) {
            float s[2][4];
            #pragma unroll
            for (int dy = 0; dy < 2; dy++) {
                int row = ty + dy * 16 + kh;
                #pragma unroll
                for (int j = 0; j < 2; j++) {
                    float2 v2 = *(const float2*)(sIn + row * 36 + 2 * tx + 2 * j);
                    s[dy][2 * j] = v2.x; s[dy][2 * j + 1] = v2.y;
                }
            }
            #pragma unroll
            for (int kw = 0; kw < 3; kw++) {
                int k = kh * 3 + kw;
                ulonglong2 wA = *(const ulonglong2*)(sW + k * 8);
                ulonglong2 wB = *(const ulonglong2*)(sW + k * 8 + 4);
                #pragma unroll
                for (int dy = 0; dy < 2; dy++)
                    #pragma unroll
                    for (int dx = 0; dx < 2; dx++) {
                        float v = s[dy][kw + dx];
                        uint64_t vv = f2pk(v, v);
                        ffma2(acc2[0][dy][dx], vv, wA.x);
                        ffma2(acc2[1][dy][dx], vv, wA.y);
                        ffma2(acc2[2][dy][dx], vv, wB.x);
                        ffma2(acc2[3][dy][dx], vv, wB.y);
                    }
            }
        }
        __syncthreads();
    }

    #pragma unroll
    for (int p = 0; p < 4; p++) {
        int oc0 = oc_base + 2 * p, oc1 = oc0 + 1;
        float sc0 = bn[oc0] * rsqrtf(bn[192 + oc0] + 1e-5f);
        float of0 = (bias[oc0] - bn[128 + oc0]) * sc0 + bn[64 + oc0];
        float sc1 = bn[oc1] * rsqrtf(bn[192 + oc1] + 1e-5f);
        float of1 = (bias[oc1] - bn[128 + oc1]) * sc1 + bn[64 + oc1];
        #pragma unroll
        for (int dy = 0; dy < 2; dy++) {
            int y = by * 32 + ty + dy * 16, xx = bx * 32 + 2 * tx;
            float2 a0 = f2un(acc2[p][dy][0]);
            float2 a1 = f2un(acc2[p][dy][1]);
            float2 v0, v1;
            v0.x = fmaxf(fmaf(a0.x, sc0, of0), 0.0f);
            v0.y = fmaxf(fmaf(a1.x, sc0, of0), 0.0f);
            v1.x = fmaxf(fmaf(a0.y, sc1, of1), 0.0f);
            v1.y = fmaxf(fmaf(a1.y, sc1, of1), 0.0f);
            *(float2*)(out + ((b * C1 + oc0) * H2 + y) * W2 + xx) = v0;
            *(float2*)(out + ((b * C1 + oc1) * H2 + y) * W2 + xx) = v1;
        }
    }
}

// ---------------------------------------------------------------------------
// 7) out-conv 7x7 (64->1, 128x128) + bias
// ---------------------------------------------------------------------------
__global__ __launch_bounds__(256) void out_conv_kernel(
    const float* __restrict__ rin, const float* __restrict__ w,
    const float* __restrict__ bias, float* __restrict__ out)
{
    __shared__ float sIn[22 * 22];
    __shared__ float sW[49];
    int tid = threadIdx.x, tx = tid & 15, ty = tid >> 4;
    int bx = blockIdx.x, by = blockIdx.y, b = blockIdx.z;
    int y0 = by * 16 - 3, x0 = bx * 16 - 3;

    float acc = 0.0f;
    for (int ci = 0; ci < C1; ci++) {
        const float* xin = rin + (b * C1 + ci) * H2 * W2;
        for (int i = tid; i < 22 * 22; i += 256) {
            int r = i / 22, c = i % 22, gy = y0 + r, gx = x0 + c;
            sIn[i] = (gy >= 0 && gy < H2 && gx >= 0 && gx < W2) ? xin[gy * W2 + gx] : 0.0f;
        }
        if (tid < 49) sW[tid] = w[ci * 49 + tid];
        __syncthreads();
        #pragma unroll 1
        for (int kh = 0; kh < 7; kh++)
            #pragma unroll
            for (int kw = 0; kw < 7; kw++)
                acc = fmaf(sIn[(ty + kh) * 22 + (tx + kw)], sW[kh * 7 + kw], acc);
        __syncthreads();
    }
    out[b * H2 * W2 + (by * 16 + ty) * W2 + bx * 16 + tx] = acc + bias[0];
}

// ---------------------------------------------------------------------------
extern "C" void kernel_launch(void* const* d_in, const int* in_sizes, int n_in,
                              void* d_out, int out_size) {
    const float* cur_x   = (const float*)d_in[0];
    const float* dep_x   = (const float*)d_in[1];
    const float* in_map  = (const float*)d_in[2];
    const float* up_w    = (const float*)d_in[3];
    const float* up_b    = (const float*)d_in[4];
    const float* up_bn   = (const float*)d_in[5];
    const float* conv2_w = (const float*)d_in[6];
    const float* conv2_b = (const float*)d_in[7];
    const float* d1_w    = (const float*)d_in[8];
    const float* d1_b    = (const float*)d_in[9];
    const float* d1_bn   = (const float*)d_in[10];
    const float* d2_w    = (const float*)d_in[11];
    const float* d2_b    = (const float*)d_in[12];
    const float* d2_bn   = (const float*)d_in[13];
    const float* d3_w    = (const float*)d_in[14];
    const float* d3_b    = (const float*)d_in[15];
    const float* d3_bn   = (const float*)d_in[16];
    const float* out_w   = (const float*)d_in[17];
    const float* out_b   = (const float*)d_in[18];
    const float* beta    = (const float*)d_in[19];
    float* out = (float*)d_out;

    float *p_t1, *p_r1, *p_r2;
    cudaGetSymbolAddress((void**)&p_t1, g_t1);
    cudaGetSymbolAddress((void**)&p_r1, g_r1);
    cudaGetSymbolAddress((void**)&p_r2, g_r2);

    upsample_sig_kernel<<<MAP_ELEMS / 256, 256>>>(in_map);
    inc_kernel<<<MAP_ELEMS / 256, 256>>>();
    outmap_kernel<<<MAP_ELEMS / 256, 256>>>();

    up_conv_kernel<<<dim3(2, 2, 256), 256>>>(dep_x, up_w, up_b, up_bn);

    conv2_kernel<<<dim3(4, 4, 64), 256>>>(cur_x, conv2_w, conv2_b, beta);

    conv3_bn_relu_kernel<<<dim3(4, 4, 64), 256>>>(p_t1, d1_w, d1_b, d1_bn, p_r1);
    conv3_bn_relu_kernel<<<dim3(4, 4, 64), 256>>>(p_r1, d2_w, d2_b, d2_bn, p_r2);
    conv3_bn_relu_kernel<<<dim3(4, 4, 64), 256>>>(p_r2, d3_w, d3_b, d3_bn, out);

    out_conv_kernel<<<dim3(8, 8, 8), 256>>>(out, out_w, out_b, out + R_ELEMS);
}

// round 10
// speedup vs baseline: 1.8653x; 1.3283x over previous
#include <cuda_runtime.h>
#include <cuda_bf16.h>
#include <math.h>
#include <stdint.h>

#define BB 8
#define C1 64
#define C2 128
#define HH 64
#define WW 64
#define H2 128
#define W2 128

#define R_ELEMS (BB*C1*H2*W2)   /* 8388608 */
#define MAP_ELEMS (BB*H2*W2)    /* 131072  */

__device__ float g_dep[R_ELEMS];
__device__ float g_t1[R_ELEMS];
__device__ float g_r1[R_ELEMS];
__device__ float g_r2[R_ELEMS];
__device__ float g_im[MAP_ELEMS];
__device__ float g_im1[MAP_ELEMS];
__device__ float g_inc[MAP_ELEMS];
__device__ float g_outmap[MAP_ELEMS];

// transformed up-conv weights: [tap 49][oc 256][ci 128, perm within 16-chunks]
#define WQ_ELEMS (49 * 256 * 128)
__device__ __align__(16) unsigned short g_wh[WQ_ELEMS];
__device__ __align__(16) unsigned short g_wl[WQ_ELEMS];

// ---------------- helpers ----------------
__device__ __forceinline__ uint64_t f2pk(float lo, float hi) {
    uint64_t r;
    asm("mov.b64 %0, {%1, %2};" : "=l"(r) : "f"(lo), "f"(hi));
    return r;
}
__device__ __forceinline__ void ffma2(uint64_t& d, uint64_t a, uint64_t b) {
    asm("fma.rn.f32x2 %0, %1, %2, %0;" : "+l"(d) : "l"(a), "l"(b));
}
__device__ __forceinline__ float2 f2un(uint64_t v) {
    float2 r;
    asm("mov.b64 {%0, %1}, %2;" : "=f"(r.x), "=f"(r.y) : "l"(v));
    return r;
}
__device__ __forceinline__ void split_bf16(float x, unsigned short& h, unsigned short& l) {
    __nv_bfloat16 bh = __float2bfloat16(x);
    float fh = __bfloat162float(bh);
    __nv_bfloat16 bl = __float2bfloat16(x - fh);
    h = *reinterpret_cast<unsigned short*>(&bh);
    l = *reinterpret_cast<unsigned short*>(&bl);
}
__device__ __forceinline__ void mma16816(float* d,
    uint32_t a0, uint32_t a1, uint32_t a2, uint32_t a3,
    uint32_t b0, uint32_t b1)
{
    asm volatile(
        "mma.sync.aligned.m16n8k16.row.col.f32.bf16.bf16.f32 "
        "{%0,%1,%2,%3}, {%4,%5,%6,%7}, {%8,%9}, {%0,%1,%2,%3};"
        : "+f"(d[0]), "+f"(d[1]), "+f"(d[2]), "+f"(d[3])
        : "r"(a0), "r"(a1), "r"(a2), "r"(a3), "r"(b0), "r"(b1));
}

// ---------------- weight prep: w[oc][ci][7][7] -> W''[tap][oc][ci-perm] hi/lo ----
__global__ void prep_w_kernel(const float* __restrict__ w) {
    int idx = blockIdx.x * blockDim.x + threadIdx.x;
    if (idx >= WQ_ELEMS) return;
    int cix = idx & 127, oc = (idx >> 7) & 255, tap = idx >> 15;
    int p = cix & 15, chunk = cix >> 4;
    int ci = chunk * 16 + 2 * (p >> 2) + (p & 1) + 8 * ((p >> 1) & 1);
    float v = w[(oc * 128 + ci) * 49 + tap];
    unsigned short h, l;
    split_bf16(v, h, l);
    g_wh[idx] = h;
    g_wl[idx] = l;
}

// ---------------- up-conv via mma.sync bf16x3 implicit GEMM ----------------
// CTA: 64 oc x 128 px (2 image rows). grid (4 ocblk, 256 ntile).
// X smem tile: [8 rows][72 cols][16 ci-perm] bf16 hi/lo, rebuilt per ci-chunk.
__global__ __launch_bounds__(256) void up_mma_kernel(
    const float* __restrict__ x, const float* __restrict__ bias,
    const float* __restrict__ bn)
{
    __shared__ __align__(16) unsigned short Xh[8 * 72 * 16];
    __shared__ __align__(16) unsigned short Xl[8 * 72 * 16];

    int tid = threadIdx.x, lane = tid & 31, wid = tid >> 5;
    int g = lane >> 2, t = lane & 3;
    int mblk = blockIdx.x;             // oc block of 64
    int ntile = blockIdx.y;            // 0..255
    int bi = ntile >> 5;
    int y0 = (ntile & 31) * 2;         // 2 image rows per CTA
    int wm = wid >> 2, wn = wid & 3;   // warp 32oc x 32px
    int wy = wn >> 1;                  // 0..1 image row
    int wx = (wn & 1) * 32;            // col offset
    int ocb = mblk * 64 + wm * 32;

    float acc[2][4][4];
    #pragma unroll
    for (int mf = 0; mf < 2; mf++)
        #pragma unroll
        for (int nf = 0; nf < 4; nf++)
            #pragma unroll
            for (int e = 0; e < 4; e++) acc[mf][nf][e] = 0.0f;

    for (int chunk = 0; chunk < 8; chunk++) {
        __syncthreads();
        // fill X tile (rows y0-3..y0+4, cols -3..68, 16 permuted ci)
        #pragma unroll 4
        for (int it = 0; it < 36; it++) {
            int idx = tid + it * 256;
            int c = idx % 72;
            int r = (idx / 72) & 7;
            int p = idx / 576;
            int ci = chunk * 16 + 2 * (p >> 2) + (p & 1) + 8 * ((p >> 1) & 1);
            int gy = y0 - 3 + r, gx = c - 3;
            float v = 0.0f;
            if (gy >= 0 && gy < 64 && gx >= 0 && gx < 64)
                v = x[((bi * C2 + ci) << 12) + (gy << 6) + gx];
            unsigned short h, l;
            split_bf16(v, h, l);
            int st = (r * 72 + c) * 16 + p;
            Xh[st] = h;
            Xl[st] = l;
        }
        __syncthreads();

        for (int kh = 0; kh < 7; kh++) {
            #pragma unroll
            for (int kw = 0; kw < 7; kw++) {
                int tap = kh * 7 + kw;
                size_t aoff = ((size_t)(tap * 256 + ocb + g) << 7) + chunk * 16 + t * 4;
                // A fragments: {a0=.x(row g,klo), a2=.y(row g,khi)} etc.
                uint2 ah00 = *(const uint2*)(g_wh + aoff);
                uint2 ah01 = *(const uint2*)(g_wh + aoff + (8 << 7));
                uint2 ah10 = *(const uint2*)(g_wh + aoff + (16 << 7));
                uint2 ah11 = *(const uint2*)(g_wh + aoff + (24 << 7));
                uint2 al00 = *(const uint2*)(g_wl + aoff);
                uint2 al01 = *(const uint2*)(g_wl + aoff + (8 << 7));
                uint2 al10 = *(const uint2*)(g_wl + aoff + (16 << 7));
                uint2 al11 = *(const uint2*)(g_wl + aoff + (24 << 7));
                int brow = wy + kh;
                int bcol = wx + kw + g;
                #pragma unroll
                for (int nf = 0; nf < 4; nf++) {
                    int spos = ((brow * 72 + bcol + nf * 8) << 4) + t * 4;
                    uint2 bh = *(const uint2*)(Xh + spos);
                    uint2 bl = *(const uint2*)(Xl + spos);
                    mma16816(acc[0][nf], ah00.x, ah01.x, ah00.y, ah01.y, bh.x, bh.y);
                    mma16816(acc[1][nf], ah10.x, ah11.x, ah10.y, ah11.y, bh.x, bh.y);
                    mma16816(acc[0][nf], al00.x, al01.x, al00.y, al01.y, bh.x, bh.y);
                    mma16816(acc[1][nf], al10.x, al11.x, al10.y, al11.y, bh.x, bh.y);
                    mma16816(acc[0][nf], ah00.x, ah01.x, ah00.y, ah01.y, bl.x, bl.y);
                    mma16816(acc[1][nf], ah10.x, ah11.x, ah10.y, ah11.y, bl.x, bl.y);
                }
            }
        }
    }

    // epilogue: BN + ReLU + pixel-shuffle scatter
    int yy = y0 + wy;
    #pragma unroll
    for (int mf = 0; mf < 2; mf++) {
        #pragma unroll
        for (int half = 0; half < 2; half++) {
            int oc = ocb + mf * 16 + g + half * 8;
            float scale = bn[oc] * rsqrtf(bn[768 + oc] + 1e-5f);
            float off = (bias[oc] - bn[512 + oc]) * scale + bn[256 + oc];
            int c = oc >> 2, a = (oc >> 1) & 1, d = oc & 1;
            size_t rowb = ((size_t)(bi * C1 + c) * H2 + 2 * yy + a) * W2 + d;
            #pragma unroll
            for (int nf = 0; nf < 4; nf++) {
                #pragma unroll
                for (int e = 0; e < 2; e++) {
                    float v = acc[mf][nf][half * 2 + e];
                    int col = wx + nf * 8 + 2 * t + e;
                    g_dep[rowb + 2 * col] = fmaxf(fmaf(v, scale, off), 0.0f);
                }
            }
        }
    }
}

// ---------------------------------------------------------------------------
// map pipeline
// ---------------------------------------------------------------------------
__global__ void upsample_sig_kernel(const float* __restrict__ in_map) {
    int idx = blockIdx.x * blockDim.x + threadIdx.x;
    if (idx >= MAP_ELEMS) return;
    int b = idx / (H2 * W2), p = idx % (H2 * W2);
    int oy = p / W2, ox = p % W2;
    float cy = oy * (63.0f / 127.0f), cx = ox * (63.0f / 127.0f);
    int y0 = (int)floorf(cy); int y1 = min(y0 + 1, HH - 1);
    int x0 = (int)floorf(cx); int x1 = min(x0 + 1, WW - 1);
    float wy = cy - y0, wx = cx - x0;
    const float* m = in_map + b * HH * WW;
    float u = m[y0 * WW + x0] * (1.f - wy) * (1.f - wx) + m[y0 * WW + x1] * (1.f - wy) * wx
            + m[y1 * WW + x0] * wy * (1.f - wx)         + m[y1 * WW + x1] * wy * wx;
    g_im[idx]  = 1.0f / (1.0f + expf(-u));
    g_im1[idx] = 1.0f / (1.0f + expf(-(1.0f - u)));
}

__device__ __forceinline__ float max3x3(const float* m, int oy, int ox) {
    float mx = -3.4e38f;
    #pragma unroll
    for (int dy = -1; dy <= 1; dy++) {
        int y = oy + dy;
        if (y < 0 || y >= H2) continue;
        #pragma unroll
        for (int dx = -1; dx <= 1; dx++) {
            int x = ox + dx;
            if (x < 0 || x >= W2) continue;
            mx = fmaxf(mx, m[y * W2 + x]);
        }
    }
    return mx;
}

__global__ void inc_kernel() {
    int idx = blockIdx.x * blockDim.x + threadIdx.x;
    if (idx >= MAP_ELEMS) return;
    int b = idx / (H2 * W2), p = idx % (H2 * W2);
    const float* m = g_im + b * H2 * W2;
    g_inc[idx] = max3x3(m, p / W2, p % W2) - m[p];
}

__global__ void outmap_kernel() {
    int idx = blockIdx.x * blockDim.x + threadIdx.x;
    if (idx >= MAP_ELEMS) return;
    int b = idx / (H2 * W2), p = idx % (H2 * W2);
    const float* mi = g_inc + b * H2 * W2;
    const float* m1 = g_im1 + b * H2 * W2;
    g_outmap[idx] = max3x3(mi, p / W2, p % W2) + max3x3(m1, p / W2, p % W2) - m1[p];
}

// ---------------------------------------------------------------------------
// conv2 3x3 (gated) -> t1 ; FFMA2 path
// ---------------------------------------------------------------------------
__global__ __launch_bounds__(256) void conv2_kernel(
    const float* __restrict__ x, const float* __restrict__ w,
    const float* __restrict__ bias, const float* __restrict__ beta)
{
    __shared__ float sIn[34 * 36];
    __shared__ float sMap[34 * 36];
    __shared__ __align__(16) float sW[9 * 8];
    int tid = threadIdx.x, tx = tid & 15, ty = tid >> 4;
    int bx = blockIdx.x, by = blockIdx.y;
    int b = blockIdx.z >> 3, oc_base = (blockIdx.z & 7) * 8;
    int y0 = by * 32 - 1, x0 = bx * 32 - 1;

    const float* om = g_outmap + b * H2 * W2;
    for (int i = tid; i < 34 * 34; i += 256) {
        int r = i / 34, c = i % 34, gy = y0 + r, gx = x0 + c;
        sMap[r * 36 + c] = (gy >= 0 && gy < H2 && gx >= 0 && gx < W2) ? om[gy * W2 + gx] : 0.0f;
    }
    __syncthreads();

    uint64_t acc2[4][2][2];
    #pragma unroll
    for (int p = 0; p < 4; p++)
        #pragma unroll
        for (int dy = 0; dy < 2; dy++)
            #pragma unroll
            for (int dx = 0; dx < 2; dx++) acc2[p][dy][dx] = 0ull;

    for (int ci = 0; ci < C1; ci++) {
        const float* xin = x + (b * C1 + ci) * H2 * W2;
        for (int i = tid; i < 34 * 34; i += 256) {
            int r = i / 34, c = i % 34, gy = y0 + r, gx = x0 + c;
            float v = (gy >= 0 && gy < H2 && gx >= 0 && gx < W2) ? xin[gy * W2 + gx] : 0.0f;
            sIn[r * 36 + c] = v * sMap[r * 36 + c];
        }
        for (int i = tid; i < 72; i += 256)
            sW[i] = w[((oc_base + (i & 7)) * C1 + ci) * 9 + (i >> 3)];
        __syncthreads();
        #pragma unroll
        for (int kh = 0; kh < 3; kh++) {
            float s[2][4];
            #pragma unroll
            for (int dy = 0; dy < 2; dy++) {
                int row = ty + dy * 16 + kh;
                #pragma unroll
                for (int j = 0; j < 2; j++) {
                    float2 v2 = *(const float2*)(sIn + row * 36 + 2 * tx + 2 * j);
                    s[dy][2 * j] = v2.x; s[dy][2 * j + 1] = v2.y;
                }
            }
            #pragma unroll
            for (int kw = 0; kw < 3; kw++) {
                int k = kh * 3 + kw;
                ulonglong2 wA = *(const ulonglong2*)(sW + k * 8);
                ulonglong2 wB = *(const ulonglong2*)(sW + k * 8 + 4);
                #pragma unroll
                for (int dy = 0; dy < 2; dy++)
                    #pragma unroll
                    for (int dx = 0; dx < 2; dx++) {
                        float v = s[dy][kw + dx];
                        uint64_t vv = f2pk(v, v);
                        ffma2(acc2[0][dy][dx], vv, wA.x);
                        ffma2(acc2[1][dy][dx], vv, wA.y);
                        ffma2(acc2[2][dy][dx], vv, wB.x);
                        ffma2(acc2[3][dy][dx], vv, wB.y);
                    }
            }
        }
        __syncthreads();
    }

    float bt = beta[0];
    #pragma unroll
    for (int p = 0; p < 4; p++) {
        #pragma unroll
        for (int dy = 0; dy < 2; dy++)
            #pragma unroll
            for (int dx = 0; dx < 2; dx++) {
                float2 tt = f2un(acc2[p][dy][dx]);
                int y = by * 32 + ty + dy * 16, xx = bx * 32 + 2 * tx + dx;
                int oc0 = oc_base + 2 * p;
                int i0 = ((b * C1 + oc0) * H2 + y) * W2 + xx;
                int i1 = i0 + H2 * W2;
                g_t1[i0] = g_dep[i0] + bt * (tt.x + bias[oc0]);
                g_t1[i1] = g_dep[i1] + bt * (tt.y + bias[oc0 + 1]);
            }
    }
}

// ---------------------------------------------------------------------------
// conv3x3 + BN + ReLU ; FFMA2 path
// ---------------------------------------------------------------------------
__global__ __launch_bounds__(256) void conv3_bn_relu_kernel(
    const float* __restrict__ in, const float* __restrict__ w,
    const float* __restrict__ bias, const float* __restrict__ bn,
    float* __restrict__ out)
{
    __shared__ float sIn[34 * 36];
    __shared__ __align__(16) float sW[9 * 8];
    int tid = threadIdx.x, tx = tid & 15, ty = tid >> 4;
    int bx = blockIdx.x, by = blockIdx.y;
    int b = blockIdx.z >> 3, oc_base = (blockIdx.z & 7) * 8;
    int y0 = by * 32 - 1, x0 = bx * 32 - 1;

    uint64_t acc2[4][2][2];
    #pragma unroll
    for (int p = 0; p < 4; p++)
        #pragma unroll
        for (int dy = 0; dy < 2; dy++)
            #pragma unroll
            for (int dx = 0; dx < 2; dx++) acc2[p][dy][dx] = 0ull;

    for (int ci = 0; ci < C1; ci++) {
        const float* xin = in + (b * C1 + ci) * H2 * W2;
        for (int i = tid; i < 34 * 34; i += 256) {
            int r = i / 34, c = i % 34, gy = y0 + r, gx = x0 + c;
            sIn[r * 36 + c] = (gy >= 0 && gy < H2 && gx >= 0 && gx < W2) ? xin[gy * W2 + gx] : 0.0f;
        }
        for (int i = tid; i < 72; i += 256)
            sW[i] = w[((oc_base + (i & 7)) * C1 + ci) * 9 + (i >> 3)];
        __syncthreads();
        #pragma unroll
        for (int kh = 0; kh < 3; kh++) {
            float s[2][4];
            #pragma unroll
            for (int dy = 0; dy < 2; dy++) {
                int row = ty + dy * 16 + kh;
                #pragma unroll
                for (int j = 0; j < 2; j++) {
                    float2 v2 = *(const float2*)(sIn + row * 36 + 2 * tx + 2 * j);
                    s[dy][2 * j] = v2.x; s[dy][2 * j + 1] = v2.y;
                }
            }
            #pragma unroll
            for (int kw = 0; kw < 3; kw++) {
                int k = kh * 3 + kw;
                ulonglong2 wA = *(const ulonglong2*)(sW + k * 8);
                ulonglong2 wB = *(const ulonglong2*)(sW + k * 8 + 4);
                #pragma unroll
                for (int dy = 0; dy < 2; dy++)
                    #pragma unroll
                    for (int dx = 0; dx < 2; dx++) {
                        float v = s[dy][kw + dx];
                        uint64_t vv = f2pk(v, v);
                        ffma2(acc2[0][dy][dx], vv, wA.x);
                        ffma2(acc2[1][dy][dx], vv, wA.y);
                        ffma2(acc2[2][dy][dx], vv, wB.x);
                        ffma2(acc2[3][dy][dx], vv, wB.y);
                    }
            }
        }
        __syncthreads();
    }

    #pragma unroll
    for (int p = 0; p < 4; p++) {
        int oc0 = oc_base + 2 * p, oc1 = oc0 + 1;
        float sc0 = bn[oc0] * rsqrtf(bn[192 + oc0] + 1e-5f);
        float of0 = (bias[oc0] - bn[128 + oc0]) * sc0 + bn[64 + oc0];
        float sc1 = bn[oc1] * rsqrtf(bn[192 + oc1] + 1e-5f);
        float of1 = (bias[oc1] - bn[128 + oc1]) * sc1 + bn[64 + oc1];
        #pragma unroll
        for (int dy = 0; dy < 2; dy++) {
            int y = by * 32 + ty + dy * 16, xx = bx * 32 + 2 * tx;
            float2 a0 = f2un(acc2[p][dy][0]);
            float2 a1 = f2un(acc2[p][dy][1]);
            float2 v0, v1;
            v0.x = fmaxf(fmaf(a0.x, sc0, of0), 0.0f);
            v0.y = fmaxf(fmaf(a1.x, sc0, of0), 0.0f);
            v1.x = fmaxf(fmaf(a0.y, sc1, of1), 0.0f);
            v1.y = fmaxf(fmaf(a1.y, sc1, of1), 0.0f);
            *(float2*)(out + ((b * C1 + oc0) * H2 + y) * W2 + xx) = v0;
            *(float2*)(out + ((b * C1 + oc1) * H2 + y) * W2 + xx) = v1;
        }
    }
}

// ---------------------------------------------------------------------------
// out-conv 7x7 (64->1)
// ---------------------------------------------------------------------------
__global__ __launch_bounds__(256) void out_conv_kernel(
    const float* __restrict__ rin, const float* __restrict__ w,
    const float* __restrict__ bias, float* __restrict__ out)
{
    __shared__ float sIn[22 * 22];
    __shared__ float sW[49];
    int tid = threadIdx.x, tx = tid & 15, ty = tid >> 4;
    int bx = blockIdx.x, by = blockIdx.y, b = blockIdx.z;
    int y0 = by * 16 - 3, x0 = bx * 16 - 3;

    float acc = 0.0f;
    for (int ci = 0; ci < C1; ci++) {
        const float* xin = rin + (b * C1 + ci) * H2 * W2;
        for (int i = tid; i < 22 * 22; i += 256) {
            int r = i / 22, c = i % 22, gy = y0 + r, gx = x0 + c;
            sIn[i] = (gy >= 0 && gy < H2 && gx >= 0 && gx < W2) ? xin[gy * W2 + gx] : 0.0f;
        }
        if (tid < 49) sW[tid] = w[ci * 49 + tid];
        __syncthreads();
        #pragma unroll 1
        for (int kh = 0; kh < 7; kh++)
            #pragma unroll
            for (int kw = 0; kw < 7; kw++)
                acc = fmaf(sIn[(ty + kh) * 22 + (tx + kw)], sW[kh * 7 + kw], acc);
        __syncthreads();
    }
    out[b * H2 * W2 + (by * 16 + ty) * W2 + bx * 16 + tx] = acc + bias[0];
}

// ---------------------------------------------------------------------------
extern "C" void kernel_launch(void* const* d_in, const int* in_sizes, int n_in,
                              void* d_out, int out_size) {
    const float* cur_x   = (const float*)d_in[0];
    const float* dep_x   = (const float*)d_in[1];
    const float* in_map  = (const float*)d_in[2];
    const float* up_w    = (const float*)d_in[3];
    const float* up_b    = (const float*)d_in[4];
    const float* up_bn   = (const float*)d_in[5];
    const float* conv2_w = (const float*)d_in[6];
    const float* conv2_b = (const float*)d_in[7];
    const float* d1_w    = (const float*)d_in[8];
    const float* d1_b    = (const float*)d_in[9];
    const float* d1_bn   = (const float*)d_in[10];
    const float* d2_w    = (const float*)d_in[11];
    const float* d2_b    = (const float*)d_in[12];
    const float* d2_bn   = (const float*)d_in[13];
    const float* d3_w    = (const float*)d_in[14];
    const float* d3_b    = (const float*)d_in[15];
    const float* d3_bn   = (const float*)d_in[16];
    const float* out_w   = (const float*)d_in[17];
    const float* out_b   = (const float*)d_in[18];
    const float* beta    = (const float*)d_in[19];
    float* out = (float*)d_out;

    float *p_t1, *p_r1, *p_r2;
    cudaGetSymbolAddress((void**)&p_t1, g_t1);
    cudaGetSymbolAddress((void**)&p_r1, g_r1);
    cudaGetSymbolAddress((void**)&p_r2, g_r2);

    prep_w_kernel<<<(WQ_ELEMS + 255) / 256, 256>>>(up_w);
    upsample_sig_kernel<<<MAP_ELEMS / 256, 256>>>(in_map);
    inc_kernel<<<MAP_ELEMS / 256, 256>>>();
    outmap_kernel<<<MAP_ELEMS / 256, 256>>>();

    up_mma_kernel<<<dim3(4, 256), 256>>>(dep_x, up_b, up_bn);

    conv2_kernel<<<dim3(4, 4, 64), 256>>>(cur_x, conv2_w, conv2_b, beta);

    conv3_bn_relu_kernel<<<dim3(4, 4, 64), 256>>>(p_t1, d1_w, d1_b, d1_bn, p_r1);
    conv3_bn_relu_kernel<<<dim3(4, 4, 64), 256>>>(p_r1, d2_w, d2_b, d2_bn, p_r2);
    conv3_bn_relu_kernel<<<dim3(4, 4, 64), 256>>>(p_r2, d3_w, d3_b, d3_bn, out);

    out_conv_kernel<<<dim3(8, 8, 8), 256>>>(out, out_w, out_b, out + R_ELEMS);
}

// round 11
// speedup vs baseline: 2.5025x; 1.3416x over previous
#include <cuda_runtime.h>
#include <cuda_bf16.h>
#include <math.h>
#include <stdint.h>

#define BB 8
#define C1 64
#define C2 128
#define HH 64
#define WW 64
#define H2 128
#define W2 128

#define R_ELEMS (BB*C1*H2*W2)   /* 8388608 */
#define MAP_ELEMS (BB*H2*W2)    /* 131072  */

__device__ float g_dep[R_ELEMS];
__device__ float g_t1[R_ELEMS];
__device__ float g_r1[R_ELEMS];
__device__ float g_r2[R_ELEMS];
__device__ float g_im[MAP_ELEMS];
__device__ float g_im1[MAP_ELEMS];
__device__ float g_inc[MAP_ELEMS];
__device__ float g_outmap[MAP_ELEMS];

// transformed up-conv weights: [tap 49][oc 256][ci 128 perm] hi/lo
#define WQ_ELEMS (49 * 256 * 128)
__device__ __align__(16) unsigned short g_wh[WQ_ELEMS];
__device__ __align__(16) unsigned short g_wl[WQ_ELEMS];
// transformed 3x3 weights: 4 slots of [tap 9][oc 64][ci 64 perm] hi/lo
#define W3_ELEMS (9 * 64 * 64)
__device__ __align__(16) unsigned short g_w3h[4 * W3_ELEMS];
__device__ __align__(16) unsigned short g_w3l[4 * W3_ELEMS];

// ---------------- helpers ----------------
__device__ __forceinline__ void split_bf16(float x, unsigned short& h, unsigned short& l) {
    __nv_bfloat16 bh = __float2bfloat16(x);
    float fh = __bfloat162float(bh);
    __nv_bfloat16 bl = __float2bfloat16(x - fh);
    h = *reinterpret_cast<unsigned short*>(&bh);
    l = *reinterpret_cast<unsigned short*>(&bl);
}
__device__ __forceinline__ void mma16816(float* d,
    uint32_t a0, uint32_t a1, uint32_t a2, uint32_t a3,
    uint32_t b0, uint32_t b1)
{
    asm volatile(
        "mma.sync.aligned.m16n8k16.row.col.f32.bf16.bf16.f32 "
        "{%0,%1,%2,%3}, {%4,%5,%6,%7}, {%8,%9}, {%0,%1,%2,%3};"
        : "+f"(d[0]), "+f"(d[1]), "+f"(d[2]), "+f"(d[3])
        : "r"(a0), "r"(a1), "r"(a2), "r"(a3), "r"(b0), "r"(b1));
}

// ---------------- weight prep ----------------
__global__ void prep_w_kernel(const float* __restrict__ w) {
    int idx = blockIdx.x * blockDim.x + threadIdx.x;
    if (idx >= WQ_ELEMS) return;
    int cix = idx & 127, oc = (idx >> 7) & 255, tap = idx >> 15;
    int p = cix & 15, chunk = cix >> 4;
    int ci = chunk * 16 + 2 * (p >> 2) + (p & 1) + 8 * ((p >> 1) & 1);
    float v = w[(oc * 128 + ci) * 49 + tap];
    unsigned short h, l;
    split_bf16(v, h, l);
    g_wh[idx] = h;
    g_wl[idx] = l;
}
__global__ void prep_w3_kernel(const float* __restrict__ w, int slot) {
    int idx = blockIdx.x * blockDim.x + threadIdx.x;
    if (idx >= W3_ELEMS) return;
    int cix = idx & 63, oc = (idx >> 6) & 63, tap = idx >> 12;
    int p = cix & 15, chunk = cix >> 4;
    int ci = chunk * 16 + 2 * (p >> 2) + (p & 1) + 8 * ((p >> 1) & 1);
    float v = w[(oc * 64 + ci) * 9 + tap];
    unsigned short h, l;
    split_bf16(v, h, l);
    g_w3h[slot * W3_ELEMS + idx] = h;
    g_w3l[slot * W3_ELEMS + idx] = l;
}

// ---------------- up-conv via mma.sync bf16x3 implicit GEMM ----------------
__global__ __launch_bounds__(256) void up_mma_kernel(
    const float* __restrict__ x, const float* __restrict__ bias,
    const float* __restrict__ bn)
{
    __shared__ __align__(16) unsigned short Xh[8 * 72 * 16];
    __shared__ __align__(16) unsigned short Xl[8 * 72 * 16];

    int tid = threadIdx.x, lane = tid & 31, wid = tid >> 5;
    int g = lane >> 2, t = lane & 3;
    int mblk = blockIdx.x;
    int ntile = blockIdx.y;
    int bi = ntile >> 5;
    int y0 = (ntile & 31) * 2;
    int wm = wid >> 2, wn = wid & 3;
    int wy = wn >> 1;
    int wx = (wn & 1) * 32;
    int ocb = mblk * 64 + wm * 32;

    float acc[2][4][4];
    #pragma unroll
    for (int mf = 0; mf < 2; mf++)
        #pragma unroll
        for (int nf = 0; nf < 4; nf++)
            #pragma unroll
            for (int e = 0; e < 4; e++) acc[mf][nf][e] = 0.0f;

    for (int chunk = 0; chunk < 8; chunk++) {
        __syncthreads();
        #pragma unroll 4
        for (int it = 0; it < 36; it++) {
            int idx = tid + it * 256;
            int c = idx % 72;
            int r = (idx / 72) & 7;
            int p = idx / 576;
            int ci = chunk * 16 + 2 * (p >> 2) + (p & 1) + 8 * ((p >> 1) & 1);
            int gy = y0 - 3 + r, gx = c - 3;
            float v = 0.0f;
            if (gy >= 0 && gy < 64 && gx >= 0 && gx < 64)
                v = x[((bi * C2 + ci) << 12) + (gy << 6) + gx];
            unsigned short h, l;
            split_bf16(v, h, l);
            int st = (r * 72 + c) * 16 + p;
            Xh[st] = h;
            Xl[st] = l;
        }
        __syncthreads();

        for (int kh = 0; kh < 7; kh++) {
            #pragma unroll
            for (int kw = 0; kw < 7; kw++) {
                int tap = kh * 7 + kw;
                size_t aoff = ((size_t)(tap * 256 + ocb + g) << 7) + chunk * 16 + t * 4;
                uint2 ah00 = *(const uint2*)(g_wh + aoff);
                uint2 ah01 = *(const uint2*)(g_wh + aoff + (8 << 7));
                uint2 ah10 = *(const uint2*)(g_wh + aoff + (16 << 7));
                uint2 ah11 = *(const uint2*)(g_wh + aoff + (24 << 7));
                uint2 al00 = *(const uint2*)(g_wl + aoff);
                uint2 al01 = *(const uint2*)(g_wl + aoff + (8 << 7));
                uint2 al10 = *(const uint2*)(g_wl + aoff + (16 << 7));
                uint2 al11 = *(const uint2*)(g_wl + aoff + (24 << 7));
                int brow = wy + kh;
                int bcol = wx + kw + g;
                #pragma unroll
                for (int nf = 0; nf < 4; nf++) {
                    int spos = ((brow * 72 + bcol + nf * 8) << 4) + t * 4;
                    uint2 bh = *(const uint2*)(Xh + spos);
                    uint2 bl = *(const uint2*)(Xl + spos);
                    mma16816(acc[0][nf], ah00.x, ah01.x, ah00.y, ah01.y, bh.x, bh.y);
                    mma16816(acc[1][nf], ah10.x, ah11.x, ah10.y, ah11.y, bh.x, bh.y);
                    mma16816(acc[0][nf], al00.x, al01.x, al00.y, al01.y, bh.x, bh.y);
                    mma16816(acc[1][nf], al10.x, al11.x, al10.y, al11.y, bh.x, bh.y);
                    mma16816(acc[0][nf], ah00.x, ah01.x, ah00.y, ah01.y, bl.x, bl.y);
                    mma16816(acc[1][nf], ah10.x, ah11.x, ah10.y, ah11.y, bl.x, bl.y);
                }
            }
        }
    }

    int yy = y0 + wy;
    #pragma unroll
    for (int mf = 0; mf < 2; mf++) {
        #pragma unroll
        for (int half = 0; half < 2; half++) {
            int oc = ocb + mf * 16 + g + half * 8;
            float scale = bn[oc] * rsqrtf(bn[768 + oc] + 1e-5f);
            float off = (bias[oc] - bn[512 + oc]) * scale + bn[256 + oc];
            int c = oc >> 2, a = (oc >> 1) & 1, d = oc & 1;
            size_t rowb = ((size_t)(bi * C1 + c) * H2 + 2 * yy + a) * W2 + d;
            #pragma unroll
            for (int nf = 0; nf < 4; nf++) {
                #pragma unroll
                for (int e = 0; e < 2; e++) {
                    float v = acc[mf][nf][half * 2 + e];
                    int col = wx + nf * 8 + 2 * t + e;
                    g_dep[rowb + 2 * col] = fmaxf(fmaf(v, scale, off), 0.0f);
                }
            }
        }
    }
}

// ---------------- 3x3 convs via mma.sync bf16x3 implicit GEMM ----------------
// CTA: 64 oc x 128 px (one image row). grid = 1024 (bi*128 + y0).
// GATED=1: input = cur_x * outmap, epilogue t1 = dep + beta*(acc+bias)
// GATED=0: plain input, epilogue BN+ReLU
template<int GATED>
__global__ __launch_bounds__(256) void conv3_mma_kernel(
    const float* __restrict__ in, int wslot,
    const float* __restrict__ bias, const float* __restrict__ bnp,
    float* __restrict__ outp)
{
    __shared__ __align__(16) unsigned short Xh[3 * 132 * 16];
    __shared__ __align__(16) unsigned short Xl[3 * 132 * 16];

    int tid = threadIdx.x, lane = tid & 31, wid = tid >> 5;
    int g = lane >> 2, t = lane & 3;
    int blk = blockIdx.x;
    int bi = blk >> 7;
    int y0 = blk & 127;
    int wm = wid >> 2, wn = wid & 3;
    int wx = wn * 32;
    int ocb = wm * 32;

    const unsigned short* wh = g_w3h + wslot * W3_ELEMS;
    const unsigned short* wl = g_w3l + wslot * W3_ELEMS;

    float acc[2][4][4];
    #pragma unroll
    for (int mf = 0; mf < 2; mf++)
        #pragma unroll
        for (int nf = 0; nf < 4; nf++)
            #pragma unroll
            for (int e = 0; e < 4; e++) acc[mf][nf][e] = 0.0f;

    for (int chunk = 0; chunk < 4; chunk++) {
        __syncthreads();
        #pragma unroll 5
        for (int it = 0; it < 25; it++) {
            int idx = tid + it * 256;
            if (idx < 3 * 132 * 16) {
                int p = idx & 15;
                int cc = (idx >> 4) % 132;
                int r = (idx >> 4) / 132;
                int ci = chunk * 16 + 2 * (p >> 2) + (p & 1) + 8 * ((p >> 1) & 1);
                int gy = y0 - 1 + r, gx = cc - 1;
                float v = 0.0f;
                if (gy >= 0 && gy < H2 && gx >= 0 && gx < W2) {
                    v = in[((bi * C1 + ci) << 14) + (gy << 7) + gx];
                    if (GATED) v *= g_outmap[(bi << 14) + (gy << 7) + gx];
                }
                unsigned short h, l;
                split_bf16(v, h, l);
                Xh[idx] = h;
                Xl[idx] = l;
            }
        }
        __syncthreads();

        #pragma unroll
        for (int kh = 0; kh < 3; kh++) {
            #pragma unroll
            for (int kw = 0; kw < 3; kw++) {
                int tap = kh * 3 + kw;
                int aoff = ((tap * 64 + ocb + g) << 6) + chunk * 16 + t * 4;
                uint2 ah00 = *(const uint2*)(wh + aoff);
                uint2 ah01 = *(const uint2*)(wh + aoff + (8 << 6));
                uint2 ah10 = *(const uint2*)(wh + aoff + (16 << 6));
                uint2 ah11 = *(const uint2*)(wh + aoff + (24 << 6));
                uint2 al00 = *(const uint2*)(wl + aoff);
                uint2 al01 = *(const uint2*)(wl + aoff + (8 << 6));
                uint2 al10 = *(const uint2*)(wl + aoff + (16 << 6));
                uint2 al11 = *(const uint2*)(wl + aoff + (24 << 6));
                int bcol = wx + kw + g;
                #pragma unroll
                for (int nf = 0; nf < 4; nf++) {
                    int spos = ((kh * 132 + bcol + nf * 8) << 4) + t * 4;
                    uint2 bh = *(const uint2*)(Xh + spos);
                    uint2 bl = *(const uint2*)(Xl + spos);
                    mma16816(acc[0][nf], ah00.x, ah01.x, ah00.y, ah01.y, bh.x, bh.y);
                    mma16816(acc[1][nf], ah10.x, ah11.x, ah10.y, ah11.y, bh.x, bh.y);
                    mma16816(acc[0][nf], al00.x, al01.x, al00.y, al01.y, bh.x, bh.y);
                    mma16816(acc[1][nf], al10.x, al11.x, al10.y, al11.y, bh.x, bh.y);
                    mma16816(acc[0][nf], ah00.x, ah01.x, ah00.y, ah01.y, bl.x, bl.y);
                    mma16816(acc[1][nf], ah10.x, ah11.x, ah10.y, ah11.y, bl.x, bl.y);
                }
            }
        }
    }

    // epilogue
    if (GATED) {
        float bt = bnp[0];
        #pragma unroll
        for (int mf = 0; mf < 2; mf++) {
            #pragma unroll
            for (int half = 0; half < 2; half++) {
                int oc = ocb + mf * 16 + g + half * 8;
                float bz = bias[oc];
                size_t rowb = ((size_t)(bi * C1 + oc) << 14) + (y0 << 7);
                #pragma unroll
                for (int nf = 0; nf < 4; nf++) {
                    #pragma unroll
                    for (int e = 0; e < 2; e++) {
                        int col = wx + nf * 8 + 2 * t + e;
                        outp[rowb + col] = g_dep[rowb + col]
                            + bt * (acc[mf][nf][half * 2 + e] + bz);
                    }
                }
            }
        }
    } else {
        #pragma unroll
        for (int mf = 0; mf < 2; mf++) {
            #pragma unroll
            for (int half = 0; half < 2; half++) {
                int oc = ocb + mf * 16 + g + half * 8;
                float scale = bnp[oc] * rsqrtf(bnp[192 + oc] + 1e-5f);
                float off = (bias[oc] - bnp[128 + oc]) * scale + bnp[64 + oc];
                size_t rowb = ((size_t)(bi * C1 + oc) << 14) + (y0 << 7);
                #pragma unroll
                for (int nf = 0; nf < 4; nf++) {
                    #pragma unroll
                    for (int e = 0; e < 2; e++) {
                        int col = wx + nf * 8 + 2 * t + e;
                        float v = acc[mf][nf][half * 2 + e];
                        outp[rowb + col] = fmaxf(fmaf(v, scale, off), 0.0f);
                    }
                }
            }
        }
    }
}

// ---------------------------------------------------------------------------
// map pipeline
// ---------------------------------------------------------------------------
__global__ void upsample_sig_kernel(const float* __restrict__ in_map) {
    int idx = blockIdx.x * blockDim.x + threadIdx.x;
    if (idx >= MAP_ELEMS) return;
    int b = idx / (H2 * W2), p = idx % (H2 * W2);
    int oy = p / W2, ox = p % W2;
    float cy = oy * (63.0f / 127.0f), cx = ox * (63.0f / 127.0f);
    int y0 = (int)floorf(cy); int y1 = min(y0 + 1, HH - 1);
    int x0 = (int)floorf(cx); int x1 = min(x0 + 1, WW - 1);
    float wy = cy - y0, wx = cx - x0;
    const float* m = in_map + b * HH * WW;
    float u = m[y0 * WW + x0] * (1.f - wy) * (1.f - wx) + m[y0 * WW + x1] * (1.f - wy) * wx
            + m[y1 * WW + x0] * wy * (1.f - wx)         + m[y1 * WW + x1] * wy * wx;
    g_im[idx]  = 1.0f / (1.0f + expf(-u));
    g_im1[idx] = 1.0f / (1.0f + expf(-(1.0f - u)));
}

__device__ __forceinline__ float max3x3(const float* m, int oy, int ox) {
    float mx = -3.4e38f;
    #pragma unroll
    for (int dy = -1; dy <= 1; dy++) {
        int y = oy + dy;
        if (y < 0 || y >= H2) continue;
        #pragma unroll
        for (int dx = -1; dx <= 1; dx++) {
            int x = ox + dx;
            if (x < 0 || x >= W2) continue;
            mx = fmaxf(mx, m[y * W2 + x]);
        }
    }
    return mx;
}

__global__ void inc_kernel() {
    int idx = blockIdx.x * blockDim.x + threadIdx.x;
    if (idx >= MAP_ELEMS) return;
    int b = idx / (H2 * W2), p = idx % (H2 * W2);
    const float* m = g_im + b * H2 * W2;
    g_inc[idx] = max3x3(m, p / W2, p % W2) - m[p];
}

__global__ void outmap_kernel() {
    int idx = blockIdx.x * blockDim.x + threadIdx.x;
    if (idx >= MAP_ELEMS) return;
    int b = idx / (H2 * W2), p = idx % (H2 * W2);
    const float* mi = g_inc + b * H2 * W2;
    const float* m1 = g_im1 + b * H2 * W2;
    g_outmap[idx] = max3x3(mi, p / W2, p % W2) + max3x3(m1, p / W2, p % W2) - m1[p];
}

// ---------------------------------------------------------------------------
// out-conv 7x7 (64->1)
// ---------------------------------------------------------------------------
__global__ __launch_bounds__(256) void out_conv_kernel(
    const float* __restrict__ rin, const float* __restrict__ w,
    const float* __restrict__ bias, float* __restrict__ out)
{
    __shared__ float sIn[22 * 22];
    __shared__ float sW[49];
    int tid = threadIdx.x, tx = tid & 15, ty = tid >> 4;
    int bx = blockIdx.x, by = blockIdx.y, b = blockIdx.z;
    int y0 = by * 16 - 3, x0 = bx * 16 - 3;

    float acc = 0.0f;
    for (int ci = 0; ci < C1; ci++) {
        const float* xin = rin + (b * C1 + ci) * H2 * W2;
        for (int i = tid; i < 22 * 22; i += 256) {
            int r = i / 22, c = i % 22, gy = y0 + r, gx = x0 + c;
            sIn[i] = (gy >= 0 && gy < H2 && gx >= 0 && gx < W2) ? xin[gy * W2 + gx] : 0.0f;
        }
        if (tid < 49) sW[tid] = w[ci * 49 + tid];
        __syncthreads();
        #pragma unroll 1
        for (int kh = 0; kh < 7; kh++)
            #pragma unroll
            for (int kw = 0; kw < 7; kw++)
                acc = fmaf(sIn[(ty + kh) * 22 + (tx + kw)], sW[kh * 7 + kw], acc);
        __syncthreads();
    }
    out[b * H2 * W2 + (by * 16 + ty) * W2 + bx * 16 + tx] = acc + bias[0];
}

// ---------------------------------------------------------------------------
extern "C" void kernel_launch(void* const* d_in, const int* in_sizes, int n_in,
                              void* d_out, int out_size) {
    const float* cur_x   = (const float*)d_in[0];
    const float* dep_x   = (const float*)d_in[1];
    const float* in_map  = (const float*)d_in[2];
    const float* up_w    = (const float*)d_in[3];
    const float* up_b    = (const float*)d_in[4];
    const float* up_bn   = (const float*)d_in[5];
    const float* conv2_w = (const float*)d_in[6];
    const float* conv2_b = (const float*)d_in[7];
    const float* d1_w    = (const float*)d_in[8];
    const float* d1_b    = (const float*)d_in[9];
    const float* d1_bn   = (const float*)d_in[10];
    const float* d2_w    = (const float*)d_in[11];
    const float* d2_b    = (const float*)d_in[12];
    const float* d2_bn   = (const float*)d_in[13];
    const float* d3_w    = (const float*)d_in[14];
    const float* d3_b    = (const float*)d_in[15];
    const float* d3_bn   = (const float*)d_in[16];
    const float* out_w   = (const float*)d_in[17];
    const float* out_b   = (const float*)d_in[18];
    const float* beta    = (const float*)d_in[19];
    float* out = (float*)d_out;

    float *p_t1, *p_r1, *p_r2;
    cudaGetSymbolAddress((void**)&p_t1, g_t1);
    cudaGetSymbolAddress((void**)&p_r1, g_r1);
    cudaGetSymbolAddress((void**)&p_r2, g_r2);

    prep_w_kernel<<<(WQ_ELEMS + 255) / 256, 256>>>(up_w);
    prep_w3_kernel<<<(W3_ELEMS + 255) / 256, 256>>>(conv2_w, 0);
    prep_w3_kernel<<<(W3_ELEMS + 255) / 256, 256>>>(d1_w, 1);
    prep_w3_kernel<<<(W3_ELEMS + 255) / 256, 256>>>(d2_w, 2);
    prep_w3_kernel<<<(W3_ELEMS + 255) / 256, 256>>>(d3_w, 3);

    upsample_sig_kernel<<<MAP_ELEMS / 256, 256>>>(in_map);
    inc_kernel<<<MAP_ELEMS / 256, 256>>>();
    outmap_kernel<<<MAP_ELEMS / 256, 256>>>();

    up_mma_kernel<<<dim3(4, 256), 256>>>(dep_x, up_b, up_bn);

    conv3_mma_kernel<1><<<1024, 256>>>(cur_x, 0, conv2_b, beta, p_t1);
    conv3_mma_kernel<0><<<1024, 256>>>(p_t1, 1, d1_b, d1_bn, p_r1);
    conv3_mma_kernel<0><<<1024, 256>>>(p_r1, 2, d2_b, d2_bn, p_r2);
    conv3_mma_kernel<0><<<1024, 256>>>(p_r2, 3, d3_b, d3_bn, out);

    out_conv_kernel<<<dim3(8, 8, 8), 256>>>(out, out_w, out_b, out + R_ELEMS);
}

// round 12
// speedup vs baseline: 2.5441x; 1.0166x over previous
#include <cuda_runtime.h>
#include <cuda_bf16.h>
#include <math.h>
#include <stdint.h>

#define BB 8
#define C1 64
#define C2 128
#define HH 64
#define WW 64
#define H2 128
#define W2 128

#define R_ELEMS (BB*C1*H2*W2)   /* 8388608 */
#define MAP_ELEMS (BB*H2*W2)    /* 131072  */
#define XP_ELEMS (BB*C2*HH*WW)  /* 2097152 */

__device__ float g_dep[R_ELEMS];
__device__ float g_im[MAP_ELEMS];
__device__ float g_im1[MAP_ELEMS];
__device__ float g_inc[MAP_ELEMS];
__device__ float g_outmap[MAP_ELEMS];

// packed (bf16hi<<16 | bf16lo) tensors
__device__ unsigned int g_xpk[XP_ELEMS];   // dep_x packed
__device__ unsigned int g_gpk[R_ELEMS];    // cur_x * outmap packed
__device__ unsigned int g_t1p[R_ELEMS];
__device__ unsigned int g_r1p[R_ELEMS];
__device__ unsigned int g_r2p[R_ELEMS];

// transformed up-conv weights: [tap 49][oc 256][ci 128 perm] hi/lo
#define WQ_ELEMS (49 * 256 * 128)
__device__ __align__(16) unsigned short g_wh[WQ_ELEMS];
__device__ __align__(16) unsigned short g_wl[WQ_ELEMS];
// transformed 3x3 weights: 4 slots of [tap 9][oc 64][ci 64 perm] hi/lo
#define W3_ELEMS (9 * 64 * 64)
__device__ __align__(16) unsigned short g_w3h[4 * W3_ELEMS];
__device__ __align__(16) unsigned short g_w3l[4 * W3_ELEMS];

// ---------------- helpers ----------------
__device__ __forceinline__ void split_bf16(float x, unsigned short& h, unsigned short& l) {
    __nv_bfloat16 bh = __float2bfloat16(x);
    float fh = __bfloat162float(bh);
    __nv_bfloat16 bl = __float2bfloat16(x - fh);
    h = *reinterpret_cast<unsigned short*>(&bh);
    l = *reinterpret_cast<unsigned short*>(&bl);
}
__device__ __forceinline__ unsigned int packf(float x) {
    unsigned short h, l;
    split_bf16(x, h, l);
    return ((unsigned int)h << 16) | (unsigned int)l;
}
__device__ __forceinline__ void mma16816(float* d,
    uint32_t a0, uint32_t a1, uint32_t a2, uint32_t a3,
    uint32_t b0, uint32_t b1)
{
    asm volatile(
        "mma.sync.aligned.m16n8k16.row.col.f32.bf16.bf16.f32 "
        "{%0,%1,%2,%3}, {%4,%5,%6,%7}, {%8,%9}, {%0,%1,%2,%3};"
        : "+f"(d[0]), "+f"(d[1]), "+f"(d[2]), "+f"(d[3])
        : "r"(a0), "r"(a1), "r"(a2), "r"(a3), "r"(b0), "r"(b1));
}

// ---------------- weight prep ----------------
__global__ void prep_w_kernel(const float* __restrict__ w) {
    int idx = blockIdx.x * blockDim.x + threadIdx.x;
    if (idx >= WQ_ELEMS) return;
    int cix = idx & 127, oc = (idx >> 7) & 255, tap = idx >> 15;
    int p = cix & 15, chunk = cix >> 4;
    int ci = chunk * 16 + 2 * (p >> 2) + (p & 1) + 8 * ((p >> 1) & 1);
    float v = w[(oc * 128 + ci) * 49 + tap];
    unsigned short h, l;
    split_bf16(v, h, l);
    g_wh[idx] = h;
    g_wl[idx] = l;
}
__global__ void prep_w3_kernel(const float* __restrict__ w, int slot) {
    int idx = blockIdx.x * blockDim.x + threadIdx.x;
    if (idx >= W3_ELEMS) return;
    int cix = idx & 63, oc = (idx >> 6) & 63, tap = idx >> 12;
    int p = cix & 15, chunk = cix >> 4;
    int ci = chunk * 16 + 2 * (p >> 2) + (p & 1) + 8 * ((p >> 1) & 1);
    float v = w[(oc * 64 + ci) * 9 + tap];
    unsigned short h, l;
    split_bf16(v, h, l);
    g_w3h[slot * W3_ELEMS + idx] = h;
    g_w3l[slot * W3_ELEMS + idx] = l;
}

// ---------------- input pack kernels ----------------
__global__ void pack_dep_kernel(const float* __restrict__ x) {
    int i = blockIdx.x * blockDim.x + threadIdx.x;
    if (i < XP_ELEMS) g_xpk[i] = packf(x[i]);
}
// gated pack: cur_x[b][ci][y][x] * outmap[b][y][x]
__global__ void gate_pack_kernel(const float* __restrict__ x) {
    int i = blockIdx.x * blockDim.x + threadIdx.x;
    if (i >= R_ELEMS) return;
    int b = i >> 20;                 // 64 ch * 16384 px = 2^20
    int px = i & 16383;
    g_gpk[i] = packf(x[i] * g_outmap[(b << 14) + px]);
}

// ---------------- up-conv via mma.sync bf16x3 implicit GEMM ----------------
__global__ __launch_bounds__(256) void up_mma_kernel(
    const float* __restrict__ bias, const float* __restrict__ bn)
{
    __shared__ __align__(16) unsigned short Xh[8 * 72 * 16];
    __shared__ __align__(16) unsigned short Xl[8 * 72 * 16];

    int tid = threadIdx.x, lane = tid & 31, wid = tid >> 5;
    int g = lane >> 2, t = lane & 3;
    int mblk = blockIdx.x;
    int ntile = blockIdx.y;
    int bi = ntile >> 5;
    int y0 = (ntile & 31) * 2;
    int wm = wid >> 2, wn = wid & 3;
    int wy = wn >> 1;
    int wx = (wn & 1) * 32;
    int ocb = mblk * 64 + wm * 32;

    float acc[2][4][4];
    #pragma unroll
    for (int mf = 0; mf < 2; mf++)
        #pragma unroll
        for (int nf = 0; nf < 4; nf++)
            #pragma unroll
            for (int e = 0; e < 4; e++) acc[mf][nf][e] = 0.0f;

    for (int chunk = 0; chunk < 8; chunk++) {
        __syncthreads();
        #pragma unroll 4
        for (int it = 0; it < 36; it++) {
            int idx = tid + it * 256;
            int c = idx % 72;
            int r = (idx / 72) & 7;
            int p = idx / 576;
            int ci = chunk * 16 + 2 * (p >> 2) + (p & 1) + 8 * ((p >> 1) & 1);
            int gy = y0 - 3 + r, gx = c - 3;
            unsigned int v = 0;
            if (gy >= 0 && gy < 64 && gx >= 0 && gx < 64)
                v = g_xpk[((bi * C2 + ci) << 12) + (gy << 6) + gx];
            int st = (r * 72 + c) * 16 + p;
            Xh[st] = (unsigned short)(v >> 16);
            Xl[st] = (unsigned short)v;
        }
        __syncthreads();

        for (int kh = 0; kh < 7; kh++) {
            #pragma unroll
            for (int kw = 0; kw < 7; kw++) {
                int tap = kh * 7 + kw;
                size_t aoff = ((size_t)(tap * 256 + ocb + g) << 7) + chunk * 16 + t * 4;
                uint2 ah00 = *(const uint2*)(g_wh + aoff);
                uint2 ah01 = *(const uint2*)(g_wh + aoff + (8 << 7));
                uint2 ah10 = *(const uint2*)(g_wh + aoff + (16 << 7));
                uint2 ah11 = *(const uint2*)(g_wh + aoff + (24 << 7));
                uint2 al00 = *(const uint2*)(g_wl + aoff);
                uint2 al01 = *(const uint2*)(g_wl + aoff + (8 << 7));
                uint2 al10 = *(const uint2*)(g_wl + aoff + (16 << 7));
                uint2 al11 = *(const uint2*)(g_wl + aoff + (24 << 7));
                int brow = wy + kh;
                int bcol = wx + kw + g;
                #pragma unroll
                for (int nf = 0; nf < 4; nf++) {
                    int spos = ((brow * 72 + bcol + nf * 8) << 4) + t * 4;
                    uint2 bh = *(const uint2*)(Xh + spos);
                    uint2 bl = *(const uint2*)(Xl + spos);
                    mma16816(acc[0][nf], ah00.x, ah01.x, ah00.y, ah01.y, bh.x, bh.y);
                    mma16816(acc[1][nf], ah10.x, ah11.x, ah10.y, ah11.y, bh.x, bh.y);
                    mma16816(acc[0][nf], al00.x, al01.x, al00.y, al01.y, bh.x, bh.y);
                    mma16816(acc[1][nf], al10.x, al11.x, al10.y, al11.y, bh.x, bh.y);
                    mma16816(acc[0][nf], ah00.x, ah01.x, ah00.y, ah01.y, bl.x, bl.y);
                    mma16816(acc[1][nf], ah10.x, ah11.x, ah10.y, ah11.y, bl.x, bl.y);
                }
            }
        }
    }

    int yy = y0 + wy;
    #pragma unroll
    for (int mf = 0; mf < 2; mf++) {
        #pragma unroll
        for (int half = 0; half < 2; half++) {
            int oc = ocb + mf * 16 + g + half * 8;
            float scale = bn[oc] * rsqrtf(bn[768 + oc] + 1e-5f);
            float off = (bias[oc] - bn[512 + oc]) * scale + bn[256 + oc];
            int c = oc >> 2, a = (oc >> 1) & 1, d = oc & 1;
            size_t rowb = ((size_t)(bi * C1 + c) * H2 + 2 * yy + a) * W2 + d;
            #pragma unroll
            for (int nf = 0; nf < 4; nf++) {
                #pragma unroll
                for (int e = 0; e < 2; e++) {
                    float v = acc[mf][nf][half * 2 + e];
                    int col = wx + nf * 8 + 2 * t + e;
                    g_dep[rowb + 2 * col] = fmaxf(fmaf(v, scale, off), 0.0f);
                }
            }
        }
    }
}

// ---------------- 3x3 convs via mma.sync bf16x3 implicit GEMM ----------------
// MODE 0: epilogue t1 = dep + beta*(acc+bias), packed out (beta in bnp[0])
// MODE 1: epilogue BN+ReLU, packed out
// MODE 2: epilogue BN+ReLU, fp32 out
template<int MODE>
__global__ __launch_bounds__(256) void conv3_mma_kernel(
    const unsigned int* __restrict__ in, int wslot,
    const float* __restrict__ bias, const float* __restrict__ bnp,
    void* __restrict__ outp)
{
    __shared__ __align__(16) unsigned short Xh[3 * 132 * 16];
    __shared__ __align__(16) unsigned short Xl[3 * 132 * 16];

    int tid = threadIdx.x, lane = tid & 31, wid = tid >> 5;
    int g = lane >> 2, t = lane & 3;
    int blk = blockIdx.x;
    int bi = blk >> 7;
    int y0 = blk & 127;
    int wm = wid >> 2, wn = wid & 3;
    int wx = wn * 32;
    int ocb = wm * 32;

    const unsigned short* wh = g_w3h + wslot * W3_ELEMS;
    const unsigned short* wl = g_w3l + wslot * W3_ELEMS;

    float acc[2][4][4];
    #pragma unroll
    for (int mf = 0; mf < 2; mf++)
        #pragma unroll
        for (int nf = 0; nf < 4; nf++)
            #pragma unroll
            for (int e = 0; e < 4; e++) acc[mf][nf][e] = 0.0f;

    for (int chunk = 0; chunk < 4; chunk++) {
        __syncthreads();
        #pragma unroll 5
        for (int it = 0; it < 25; it++) {
            int idx = tid + it * 256;
            if (idx < 3 * 132 * 16) {
                int p = idx & 15;
                int cc = (idx >> 4) % 132;
                int r = (idx >> 4) / 132;
                int ci = chunk * 16 + 2 * (p >> 2) + (p & 1) + 8 * ((p >> 1) & 1);
                int gy = y0 - 1 + r, gx = cc - 1;
                unsigned int v = 0;
                if (gy >= 0 && gy < H2 && gx >= 0 && gx < W2)
                    v = in[((bi * C1 + ci) << 14) + (gy << 7) + gx];
                Xh[idx] = (unsigned short)(v >> 16);
                Xl[idx] = (unsigned short)v;
            }
        }
        __syncthreads();

        #pragma unroll
        for (int kh = 0; kh < 3; kh++) {
            #pragma unroll
            for (int kw = 0; kw < 3; kw++) {
                int tap = kh * 3 + kw;
                int aoff = ((tap * 64 + ocb + g) << 6) + chunk * 16 + t * 4;
                uint2 ah00 = *(const uint2*)(wh + aoff);
                uint2 ah01 = *(const uint2*)(wh + aoff + (8 << 6));
                uint2 ah10 = *(const uint2*)(wh + aoff + (16 << 6));
                uint2 ah11 = *(const uint2*)(wh + aoff + (24 << 6));
                uint2 al00 = *(const uint2*)(wl + aoff);
                uint2 al01 = *(const uint2*)(wl + aoff + (8 << 6));
                uint2 al10 = *(const uint2*)(wl + aoff + (16 << 6));
                uint2 al11 = *(const uint2*)(wl + aoff + (24 << 6));
                int bcol = wx + kw + g;
                #pragma unroll
                for (int nf = 0; nf < 4; nf++) {
                    int spos = ((kh * 132 + bcol + nf * 8) << 4) + t * 4;
                    uint2 bh = *(const uint2*)(Xh + spos);
                    uint2 bl = *(const uint2*)(Xl + spos);
                    mma16816(acc[0][nf], ah00.x, ah01.x, ah00.y, ah01.y, bh.x, bh.y);
                    mma16816(acc[1][nf], ah10.x, ah11.x, ah10.y, ah11.y, bh.x, bh.y);
                    mma16816(acc[0][nf], al00.x, al01.x, al00.y, al01.y, bh.x, bh.y);
                    mma16816(acc[1][nf], al10.x, al11.x, al10.y, al11.y, bh.x, bh.y);
                    mma16816(acc[0][nf], ah00.x, ah01.x, ah00.y, ah01.y, bl.x, bl.y);
                    mma16816(acc[1][nf], ah10.x, ah11.x, ah10.y, ah11.y, bl.x, bl.y);
                }
            }
        }
    }

    // epilogue
    #pragma unroll
    for (int mf = 0; mf < 2; mf++) {
        #pragma unroll
        for (int half = 0; half < 2; half++) {
            int oc = ocb + mf * 16 + g + half * 8;
            size_t rowb = ((size_t)(bi * C1 + oc) << 14) + (y0 << 7);
            if (MODE == 0) {
                float bt = bnp[0];
                float bz = bias[oc];
                unsigned int* po = (unsigned int*)outp;
                #pragma unroll
                for (int nf = 0; nf < 4; nf++)
                    #pragma unroll
                    for (int e = 0; e < 2; e++) {
                        int col = wx + nf * 8 + 2 * t + e;
                        float v = g_dep[rowb + col]
                                + bt * (acc[mf][nf][half * 2 + e] + bz);
                        po[rowb + col] = packf(v);
                    }
            } else {
                float scale = bnp[oc] * rsqrtf(bnp[192 + oc] + 1e-5f);
                float off = (bias[oc] - bnp[128 + oc]) * scale + bnp[64 + oc];
                #pragma unroll
                for (int nf = 0; nf < 4; nf++)
                    #pragma unroll
                    for (int e = 0; e < 2; e++) {
                        int col = wx + nf * 8 + 2 * t + e;
                        float v = acc[mf][nf][half * 2 + e];
                        v = fmaxf(fmaf(v, scale, off), 0.0f);
                        if (MODE == 1) ((unsigned int*)outp)[rowb + col] = packf(v);
                        else           ((float*)outp)[rowb + col] = v;
                    }
            }
        }
    }
}

// ---------------------------------------------------------------------------
// map pipeline
// ---------------------------------------------------------------------------
__global__ void upsample_sig_kernel(const float* __restrict__ in_map) {
    int idx = blockIdx.x * blockDim.x + threadIdx.x;
    if (idx >= MAP_ELEMS) return;
    int b = idx / (H2 * W2), p = idx % (H2 * W2);
    int oy = p / W2, ox = p % W2;
    float cy = oy * (63.0f / 127.0f), cx = ox * (63.0f / 127.0f);
    int y0 = (int)floorf(cy); int y1 = min(y0 + 1, HH - 1);
    int x0 = (int)floorf(cx); int x1 = min(x0 + 1, WW - 1);
    float wy = cy - y0, wx = cx - x0;
    const float* m = in_map + b * HH * WW;
    float u = m[y0 * WW + x0] * (1.f - wy) * (1.f - wx) + m[y0 * WW + x1] * (1.f - wy) * wx
            + m[y1 * WW + x0] * wy * (1.f - wx)         + m[y1 * WW + x1] * wy * wx;
    g_im[idx]  = 1.0f / (1.0f + expf(-u));
    g_im1[idx] = 1.0f / (1.0f + expf(-(1.0f - u)));
}

__device__ __forceinline__ float max3x3(const float* m, int oy, int ox) {
    float mx = -3.4e38f;
    #pragma unroll
    for (int dy = -1; dy <= 1; dy++) {
        int y = oy + dy;
        if (y < 0 || y >= H2) continue;
        #pragma unroll
        for (int dx = -1; dx <= 1; dx++) {
            int x = ox + dx;
            if (x < 0 || x >= W2) continue;
            mx = fmaxf(mx, m[y * W2 + x]);
        }
    }
    return mx;
}

__global__ void inc_kernel() {
    int idx = blockIdx.x * blockDim.x + threadIdx.x;
    if (idx >= MAP_ELEMS) return;
    int b = idx / (H2 * W2), p = idx % (H2 * W2);
    const float* m = g_im + b * H2 * W2;
    g_inc[idx] = max3x3(m, p / W2, p % W2) - m[p];
}

__global__ void outmap_kernel() {
    int idx = blockIdx.x * blockDim.x + threadIdx.x;
    if (idx >= MAP_ELEMS) return;
    int b = idx / (H2 * W2), p = idx % (H2 * W2);
    const float* mi = g_inc + b * H2 * W2;
    const float* m1 = g_im1 + b * H2 * W2;
    g_outmap[idx] = max3x3(mi, p / W2, p % W2) + max3x3(m1, p / W2, p % W2) - m1[p];
}

// ---------------------------------------------------------------------------
// out-conv 7x7 (64->1)
// ---------------------------------------------------------------------------
__global__ __launch_bounds__(256) void out_conv_kernel(
    const float* __restrict__ rin, const float* __restrict__ w,
    const float* __restrict__ bias, float* __restrict__ out)
{
    __shared__ float sIn[22 * 22];
    __shared__ float sW[49];
    int tid = threadIdx.x, tx = tid & 15, ty = tid >> 4;
    int bx = blockIdx.x, by = blockIdx.y, b = blockIdx.z;
    int y0 = by * 16 - 3, x0 = bx * 16 - 3;

    float acc = 0.0f;
    for (int ci = 0; ci < C1; ci++) {
        const float* xin = rin + (b * C1 + ci) * H2 * W2;
        for (int i = tid; i < 22 * 22; i += 256) {
            int r = i / 22, c = i % 22, gy = y0 + r, gx = x0 + c;
            sIn[i] = (gy >= 0 && gy < H2 && gx >= 0 && gx < W2) ? xin[gy * W2 + gx] : 0.0f;
        }
        if (tid < 49) sW[tid] = w[ci * 49 + tid];
        __syncthreads();
        #pragma unroll 1
        for (int kh = 0; kh < 7; kh++)
            #pragma unroll
            for (int kw = 0; kw < 7; kw++)
                acc = fmaf(sIn[(ty + kh) * 22 + (tx + kw)], sW[kh * 7 + kw], acc);
        __syncthreads();
    }
    out[b * H2 * W2 + (by * 16 + ty) * W2 + bx * 16 + tx] = acc + bias[0];
}

// ---------------------------------------------------------------------------
extern "C" void kernel_launch(void* const* d_in, const int* in_sizes, int n_in,
                              void* d_out, int out_size) {
    const float* cur_x   = (const float*)d_in[0];
    const float* dep_x   = (const float*)d_in[1];
    const float* in_map  = (const float*)d_in[2];
    const float* up_w    = (const float*)d_in[3];
    const float* up_b    = (const float*)d_in[4];
    const float* up_bn   = (const float*)d_in[5];
    const float* conv2_w = (const float*)d_in[6];
    const float* conv2_b = (const float*)d_in[7];
    const float* d1_w    = (const float*)d_in[8];
    const float* d1_b    = (const float*)d_in[9];
    const float* d1_bn   = (const float*)d_in[10];
    const float* d2_w    = (const float*)d_in[11];
    const float* d2_b    = (const float*)d_in[12];
    const float* d2_bn   = (const float*)d_in[13];
    const float* d3_w    = (const float*)d_in[14];
    const float* d3_b    = (const float*)d_in[15];
    const float* d3_bn   = (const float*)d_in[16];
    const float* out_w   = (const float*)d_in[17];
    const float* out_b   = (const float*)d_in[18];
    const float* beta    = (const float*)d_in[19];
    float* out = (float*)d_out;

    unsigned int *p_gpk, *p_t1p, *p_r1p, *p_r2p;
    cudaGetSymbolAddress((void**)&p_gpk, g_gpk);
    cudaGetSymbolAddress((void**)&p_t1p, g_t1p);
    cudaGetSymbolAddress((void**)&p_r1p, g_r1p);
    cudaGetSymbolAddress((void**)&p_r2p, g_r2p);

    prep_w_kernel<<<(WQ_ELEMS + 255) / 256, 256>>>(up_w);
    prep_w3_kernel<<<(W3_ELEMS + 255) / 256, 256>>>(conv2_w, 0);
    prep_w3_kernel<<<(W3_ELEMS + 255) / 256, 256>>>(d1_w, 1);
    prep_w3_kernel<<<(W3_ELEMS + 255) / 256, 256>>>(d2_w, 2);
    prep_w3_kernel<<<(W3_ELEMS + 255) / 256, 256>>>(d3_w, 3);
    pack_dep_kernel<<<(XP_ELEMS + 255) / 256, 256>>>(dep_x);

    upsample_sig_kernel<<<MAP_ELEMS / 256, 256>>>(in_map);
    inc_kernel<<<MAP_ELEMS / 256, 256>>>();
    outmap_kernel<<<MAP_ELEMS / 256, 256>>>();
    gate_pack_kernel<<<(R_ELEMS + 255) / 256, 256>>>(cur_x);

    up_mma_kernel<<<dim3(4, 256), 256>>>(up_b, up_bn);

    conv3_mma_kernel<0><<<1024, 256>>>(p_gpk, 0, conv2_b, beta, p_t1p);
    conv3_mma_kernel<1><<<1024, 256>>>(p_t1p, 1, d1_b, d1_bn, p_r1p);
    conv3_mma_kernel<1><<<1024, 256>>>(p_r1p, 2, d2_b, d2_bn, p_r2p);
    conv3_mma_kernel<2><<<1024, 256>>>(p_r2p, 3, d3_b, d3_bn, out);

    out_conv_kernel<<<dim3(8, 8, 8), 256>>>(out, out_w, out_b, out + R_ELEMS);
}